// round 14
// baseline (speedup 1.0000x reference)
#include <cuda_runtime.h>
#include <cuda_bf16.h>
#include <math.h>
#include <stdint.h>

#define NB     128
#define BATCH  8
#define HEADS  16
#define DM     512
#define DKH    32

// ---- scratch (device globals: no allocation allowed) ----
__device__ float g_k   [(long)BATCH*NB*NB*DM];   // 268 MB: k = key_edge@Wk+bk, layout (b,m,n,d)
__device__ float g_q   [BATCH*NB*DM];
__device__ float g_v   [BATCH*NB*DM];
__device__ float g_outS[BATCH*HEADS*NB*NB];      // out_scores (b,h,m,n)
__device__ float g_inS [BATCH*HEADS*NB*NB];      // in_scores stored transposed: (b,h,n,m)
__device__ float g_msg [BATCH*HEADS*NB*NB];      // message*adj (b,h,m,n)
__device__ float g_x   [BATCH*NB*DM];            // node_hidden (b,m,d)

// split+transposed weights (bf16): W*[n][k] hi/lo
__device__ __nv_bfloat16 g_wkh[DM*DM];
__device__ __nv_bfloat16 g_wkl[DM*DM];
__device__ __nv_bfloat16 g_weh[DM*DM];
__device__ __nv_bfloat16 g_wel[DM*DM];

// ============================================================
// helpers
// ============================================================
__device__ __forceinline__ uint32_t smem_u32(const void* p) {
    uint32_t a;
    asm("{ .reg .u64 t; cvta.to.shared.u64 t, %1; cvt.u32.u64 %0, t; }" : "=r"(a) : "l"(p));
    return a;
}
__device__ __forceinline__ void cp16(uint32_t dst, const void* src) {
    asm volatile("cp.async.cg.shared.global [%0], [%1], 16;" :: "r"(dst), "l"(src) : "memory");
}
#define CP_COMMIT() asm volatile("cp.async.commit_group;" ::: "memory")
#define CP_WAIT0()  asm volatile("cp.async.wait_group 0;" ::: "memory")

#define LDMX4(r, a) \
    asm volatile("ldmatrix.sync.aligned.m8n8.x4.shared.b16 {%0,%1,%2,%3}, [%4];" \
        : "=r"((r)[0]), "=r"((r)[1]), "=r"((r)[2]), "=r"((r)[3]) : "r"(a))

// pack two floats -> bf16x2 (x low half, y high half)
__device__ __forceinline__ uint32_t pack_bf(float x, float y) {
    uint32_t r;
    asm("cvt.rn.bf16x2.f32 %0, %1, %2;" : "=r"(r) : "f"(y), "f"(x));
    return r;
}
__device__ __forceinline__ float bf_hi(float x) {
    return __bfloat162float(__float2bfloat16(x));
}

// m16n8k16 row.col bf16 -> f32 accumulate
__device__ __forceinline__ void mma_bf16(float* d, const uint32_t* a, const uint32_t* b) {
    asm volatile(
        "mma.sync.aligned.m16n8k16.row.col.f32.bf16.bf16.f32 "
        "{%0,%1,%2,%3}, {%4,%5,%6,%7}, {%8,%9}, {%0,%1,%2,%3};"
        : "+f"(d[0]), "+f"(d[1]), "+f"(d[2]), "+f"(d[3])
        : "r"(a[0]), "r"(a[1]), "r"(a[2]), "r"(a[3]), "r"(b[0]), "r"(b[1]));
}

// ============================================================
// Weight prep (both weights in one launch; blockIdx.y selects)
// ============================================================
__global__ void wsplit_kernel(const float* __restrict__ Wk,
                              const float* __restrict__ We)
{
    const float* W = blockIdx.y ? We : Wk;
    __nv_bfloat16* Wh = blockIdx.y ? g_weh : g_wkh;
    __nv_bfloat16* Wl = blockIdx.y ? g_wel : g_wkl;
    int i = blockIdx.x * 256 + threadIdx.x;   // i = k*512 + n
    int k = i >> 9, n = i & 511;
    float x = W[i];
    __nv_bfloat16 h = __float2bfloat16(x);
    float r = x - __bfloat162float(h);
    Wh[n * DM + k] = h;
    Wl[n * DM + k] = __float2bfloat16(r);
}

// ============================================================
// HMMA split-bf16 GEMM: C[M,512] = A[M,512] @ Wt^T + bias
//   CTA tile 128x128, 256 threads (8 warps, 2M x 4N), warp 64x32.
//   k-chunk = 32, double-buffered dynamic smem, ldmatrix.x4,
//   3-term split: Ah*Bh + Ah*Bl + Al*Bh.  2 CTAs/SM.
//   USE_MSG: scale A rows by msg[b, head=c, m, n] (head == k32-chunk idx).
// ============================================================
#define APITCH 80
#define STAGE  (128 * APITCH)       // 10240 B per array
#define SMTOT  (2 * 4 * STAGE)      // 81920 B

template<bool USE_MSG>
__global__ __launch_bounds__(256, 2)
void mma_gemm(const float* __restrict__ A,
              const __nv_bfloat16* __restrict__ Bhp,
              const __nv_bfloat16* __restrict__ Blp,
              const float* __restrict__ bias,
              float* __restrict__ C,
              const float* __restrict__ msg)
{
    extern __shared__ __align__(16) uint8_t dsm[];
    const uint32_t sb = smem_u32(dsm);

    const int tid = threadIdx.x;
    const int wid = tid >> 5, lid = tid & 31;
    const int wm = wid & 1, wn = wid >> 1;
    const int g  = lid >> 2, tg = lid & 3;
    const int n0 = blockIdx.x * 128;
    const long m0 = (long)blockIdx.y * 128;

    // ---- A-load mapping: thread handles row ar, 16 fp32 at (tid&1)*16 ----
    const int ar = tid >> 1, ahalf = tid & 1;
    const long agr = m0 + ar;
    const float* Abase = A + agr * DM + ahalf * 16;
    long msgb = 0;
    if (USE_MSG) msgb = (((agr >> 14) * (long)HEADS) << 14) + (agr & 16383);

    // ---- ldmatrix lane address components ----
    const uint32_t a_lane = (uint32_t)((lid & 15) * APITCH + (lid >> 4) * 16);
    const uint32_t b_lane = (uint32_t)((((lid & 7) + ((lid & 16) ? 8 : 0)) * APITCH) + ((lid & 8) ? 16 : 0));
    const uint32_t a_warp = (uint32_t)(wm * 64 * APITCH);
    const uint32_t b_warp = (uint32_t)(wn * 32 * APITCH);

    float acc[4][4][4];
#pragma unroll
    for (int mi = 0; mi < 4; mi++)
#pragma unroll
        for (int ni = 0; ni < 4; ni++)
#pragma unroll
            for (int r = 0; r < 4; r++) acc[mi][ni][r] = 0.f;

    float areg[16];

    auto LDA = [&](int c) {
        const float* p = Abase + c * 32;
#pragma unroll
        for (int q = 0; q < 4; q++) {
            float4 v = *(const float4*)(p + q * 4);
            areg[q * 4 + 0] = v.x; areg[q * 4 + 1] = v.y;
            areg[q * 4 + 2] = v.z; areg[q * 4 + 3] = v.w;
        }
        if (USE_MSG) {
            float s = msg[msgb + ((long)c << 14)];
#pragma unroll
            for (int i = 0; i < 16; i++) areg[i] *= s;
        }
    };
    auto STA = [&](int s) {
        float h[16];
#pragma unroll
        for (int i = 0; i < 16; i++) h[i] = bf_hi(areg[i]);
        uint32_t ph[8], pl[8];
#pragma unroll
        for (int i = 0; i < 8; i++) {
            ph[i] = pack_bf(h[2*i], h[2*i+1]);
            pl[i] = pack_bf(areg[2*i] - h[2*i], areg[2*i+1] - h[2*i+1]);
        }
        const uint32_t dh = sb + (uint32_t)(s * 4 * STAGE) + (uint32_t)(ar * APITCH + ahalf * 32);
        const uint32_t dl = dh + STAGE;
        asm volatile("st.shared.v4.b32 [%0], {%1,%2,%3,%4};" :: "r"(dh),      "r"(ph[0]), "r"(ph[1]), "r"(ph[2]), "r"(ph[3]) : "memory");
        asm volatile("st.shared.v4.b32 [%0], {%1,%2,%3,%4};" :: "r"(dh + 16), "r"(ph[4]), "r"(ph[5]), "r"(ph[6]), "r"(ph[7]) : "memory");
        asm volatile("st.shared.v4.b32 [%0], {%1,%2,%3,%4};" :: "r"(dl),      "r"(pl[0]), "r"(pl[1]), "r"(pl[2]), "r"(pl[3]) : "memory");
        asm volatile("st.shared.v4.b32 [%0], {%1,%2,%3,%4};" :: "r"(dl + 16), "r"(pl[4]), "r"(pl[5]), "r"(pl[6]), "r"(pl[7]) : "memory");
    };
    auto CPB = [&](int c, int s) {
        const uint32_t db = sb + (uint32_t)(s * 4 * STAGE) + (uint32_t)(2 * STAGE);
#pragma unroll
        for (int q = 0; q < 2; q++) {
            int u = q * 256 + tid;               // 512 16B-units per array
            int row = u >> 2, seg = u & 3;
            uint32_t d = db + (uint32_t)(row * APITCH + seg * 16);
            long so = (long)(n0 + row) * DM + c * 32 + seg * 8;
            cp16(d, Bhp + so);
            cp16(d + STAGE, Blp + so);
        }
    };

    auto COMPUTE = [&](int s) {
        const uint32_t base = sb + (uint32_t)(s * 4 * STAGE);
        const uint32_t pAh = base + a_warp + a_lane;
        const uint32_t pAl = pAh + STAGE;
        const uint32_t pBh = base + (uint32_t)(2 * STAGE) + b_warp + b_lane;
        const uint32_t pBl = pBh + STAGE;
#pragma unroll
        for (int ks = 0; ks < 2; ks++) {
            const uint32_t ko = (uint32_t)(ks * 32);
            uint32_t af[4][4], bh[4][2], bl[4][2];
#pragma unroll
            for (int mi = 0; mi < 4; mi++)
                LDMX4(af[mi], pAh + ko + (uint32_t)(mi * 16 * APITCH));
#pragma unroll
            for (int p = 0; p < 2; p++) {
                uint32_t r[4];
                LDMX4(r, pBh + ko + (uint32_t)(p * 16 * APITCH));
                bh[2*p][0] = r[0]; bh[2*p][1] = r[1];
                bh[2*p+1][0] = r[2]; bh[2*p+1][1] = r[3];
            }
#pragma unroll
            for (int mi = 0; mi < 4; mi++)
#pragma unroll
                for (int ni = 0; ni < 4; ni++) mma_bf16(acc[mi][ni], af[mi], bh[ni]);
#pragma unroll
            for (int p = 0; p < 2; p++) {
                uint32_t r[4];
                LDMX4(r, pBl + ko + (uint32_t)(p * 16 * APITCH));
                bl[2*p][0] = r[0]; bl[2*p][1] = r[1];
                bl[2*p+1][0] = r[2]; bl[2*p+1][1] = r[3];
            }
#pragma unroll
            for (int mi = 0; mi < 4; mi++)
#pragma unroll
                for (int ni = 0; ni < 4; ni++) mma_bf16(acc[mi][ni], af[mi], bl[ni]);
#pragma unroll
            for (int mi = 0; mi < 4; mi++)      // reuse af regs for A-lo
                LDMX4(af[mi], pAl + ko + (uint32_t)(mi * 16 * APITCH));
#pragma unroll
            for (int mi = 0; mi < 4; mi++)
#pragma unroll
                for (int ni = 0; ni < 4; ni++) mma_bf16(acc[mi][ni], af[mi], bh[ni]);
        }
    };

    // ---- pipeline: 16 k32-chunks, double buffered ----
    LDA(0);
    CPB(0, 0); CP_COMMIT();
    STA(0);
    CP_WAIT0(); __syncthreads();
#pragma unroll 1
    for (int c = 0; c < 16; c++) {
        const int s = c & 1;
        const bool more = (c < 15);
        if (more) { CPB(c + 1, s ^ 1); CP_COMMIT(); LDA(c + 1); }
        COMPUTE(s);
        if (more) { STA(s ^ 1); CP_WAIT0(); }
        __syncthreads();
    }

    // ---- epilogue ----
#pragma unroll
    for (int ni = 0; ni < 4; ni++) {
        const int col = n0 + wn * 32 + ni * 8 + tg * 2;
        const float b0 = bias[col], b1 = bias[col + 1];
#pragma unroll
        for (int mi = 0; mi < 4; mi++) {
            const long row = m0 + wm * 64 + mi * 16 + g;
            float2 o0 = make_float2(acc[mi][ni][0] + b0, acc[mi][ni][1] + b1);
            float2 o1 = make_float2(acc[mi][ni][2] + b0, acc[mi][ni][3] + b1);
            *(float2*)(C + row * DM + col)       = o0;
            *(float2*)(C + (row + 8) * DM + col) = o1;
        }
    }
}

// ============================================================
// fp32 SGEMM 64x64 tiles for the small projections (M=1024)
// blockIdx.z selects problem {0,1} so two GEMMs batch in one launch.
// ============================================================
__global__ __launch_bounds__(256)
void sgemm64(const float* __restrict__ A0, const float* __restrict__ A1,
             const float* __restrict__ W0, const float* __restrict__ W1,
             const float* __restrict__ b0p, const float* __restrict__ b1p,
             float* __restrict__ C0, float* __restrict__ C1)
{
    const float* A    = blockIdx.z ? A1 : A0;
    const float* B    = blockIdx.z ? W1 : W0;
    const float* bias = blockIdx.z ? b1p : b0p;
    float*       C    = blockIdx.z ? C1 : C0;

    __shared__ float As[16][64];
    __shared__ float Bs[16][64];

    const int tid = threadIdx.x;
    const int m0 = blockIdx.y * 64, n0 = blockIdx.x * 64;
    const int tx = tid & 15, ty = tid >> 4;

    const int aRow = tid >> 2, aCol = (tid & 3) * 4;
    const int bRow = tid >> 4, bCol = (tid & 15) * 4;

    float acc[4][4];
#pragma unroll
    for (int i = 0; i < 4; i++)
#pragma unroll
        for (int j = 0; j < 4; j++) acc[i][j] = 0.f;

    const float* Ap = A + (long)(m0 + aRow) * DM + aCol;
    const float* Bp = B + (long)bRow * DM + n0 + bCol;

    for (int k0 = 0; k0 < DM; k0 += 16) {
        float4 av = *(const float4*)(Ap + k0);
        As[aCol + 0][aRow] = av.x;
        As[aCol + 1][aRow] = av.y;
        As[aCol + 2][aRow] = av.z;
        As[aCol + 3][aRow] = av.w;
        *(float4*)&Bs[bRow][bCol] = *(const float4*)(Bp + (long)k0 * DM);
        __syncthreads();
#pragma unroll
        for (int kk = 0; kk < 16; kk++) {
            float4 a4 = *(float4*)&As[kk][ty * 4];
            float4 b4 = *(float4*)&Bs[kk][tx * 4];
            float ar[4] = {a4.x, a4.y, a4.z, a4.w};
            float br[4] = {b4.x, b4.y, b4.z, b4.w};
#pragma unroll
            for (int i = 0; i < 4; i++)
#pragma unroll
                for (int j = 0; j < 4; j++) acc[i][j] = fmaf(ar[i], br[j], acc[i][j]);
        }
        __syncthreads();
    }

    const int c = n0 + tx * 4;
    const float4 bz = *(const float4*)&bias[c];
#pragma unroll
    for (int i = 0; i < 4; i++) {
        const long r = m0 + ty * 4 + i;
        float4 o;
        o.x = acc[i][0] + bz.x; o.y = acc[i][1] + bz.y;
        o.z = acc[i][2] + bz.z; o.w = acc[i][3] + bz.w;
        *(float4*)&C[r * DM + c] = o;
    }
}

// ============================================================
// Scores v2: shuffle-free. Block = (b,m), 256 threads.
// Thread (h = tid&15, nr = tid>>4) computes full 32-dim head dots
// for n = nr, nr+16, ..., nr+112.  Coalesced: 16 h-threads cover a
// contiguous 2 KB k-row span.  q_m head slice lives in registers.
// ============================================================
__global__ __launch_bounds__(256)
void scores_kernel()
{
    const int bm = blockIdx.x;
    const int b  = bm >> 7, m = bm & 127;
    const int tid = threadIdx.x;
    const int h  = tid & 15, nr = tid >> 4;
    const float scale = 0.17677669529663687f;   // 1/sqrt(32)

    // q_m slice for this head -> registers
    float4 qm[8];
    const float4* qmp = (const float4*)(g_q + (long)bm * DM + h * DKH);
#pragma unroll
    for (int i = 0; i < 8; i++) qm[i] = qmp[i];

    const float* kbase = g_k + (long)bm * NB * DM + h * DKH;
    const float* qb    = g_q + (long)b * NB * DM + h * DKH;
    const long obase = (((long)b * HEADS + h) * NB + m) * NB;
    const long ibase = (((long)b * HEADS + h) * NB) * NB + m;

#pragma unroll 2
    for (int it = 0; it < 8; it++) {
        const int n = nr + it * 16;
        const float4* kp = (const float4*)(kbase + (long)n * DM);
        const float4* qn = (const float4*)(qb + (long)n * DM);
        float po = 0.f, pi = 0.f;
#pragma unroll
        for (int i = 0; i < 8; i++) {
            const float4 k4 = kp[i];
            const float4 q4 = qn[i];
            po += k4.x*qm[i].x + k4.y*qm[i].y + k4.z*qm[i].z + k4.w*qm[i].w;
            pi += k4.x*q4.x   + k4.y*q4.y   + k4.z*q4.z   + k4.w*q4.w;
        }
        g_outS[obase + n]            = po * scale;
        g_inS [ibase + (long)n * NB] = pi * scale;
    }
}

// ============================================================
// Softmax + message + adj weighting.
// ============================================================
__device__ __forceinline__ float bredmax(float v, float* sm)
{
#pragma unroll
    for (int o = 16; o; o >>= 1) v = fmaxf(v, __shfl_xor_sync(0xffffffffu, v, o));
    if ((threadIdx.x & 31) == 0) sm[threadIdx.x >> 5] = v;
    __syncthreads();
    float r = fmaxf(fmaxf(sm[0], sm[1]), fmaxf(sm[2], sm[3]));
    __syncthreads();
    return r;
}
__device__ __forceinline__ float bredsum(float v, float* sm)
{
#pragma unroll
    for (int o = 16; o; o >>= 1) v += __shfl_xor_sync(0xffffffffu, v, o);
    if ((threadIdx.x & 31) == 0) sm[threadIdx.x >> 5] = v;
    __syncthreads();
    float r = sm[0] + sm[1] + sm[2] + sm[3];
    __syncthreads();
    return r;
}

__global__ void message_kernel(const float* __restrict__ adjm,
                               const int* __restrict__ mask,
                               const float* __restrict__ lam_p)
{
    const long row = blockIdx.x;
    const int i  = row & 127;
    const int b  = (int)(row >> 11);
    const int j  = threadIdx.x;
    const float lam = *lam_p;
    __shared__ float red[4];

    const int mk = mask[b * NB + j];
    const long base = row * NB;
    float so = g_outS[base + j];
    float si = g_inS [base + j];
    float aj = -lam * adjm[((long)b * NB + i) * NB + j];
    const float NEG = -3.0e38f;
    if (mk == 0) { so = NEG; si = NEG; aj = NEG; }

    const float mo = bredmax(so, red);
    const float mi = bredmax(si, red);
    const float ma = bredmax(aj, red);
    const float eo = (mk == 0) ? 0.f : expf(so - mo);
    const float ei = (mk == 0) ? 0.f : expf(si - mi);
    const float ea = (mk == 0) ? 0.f : expf(aj - ma);
    const float sumo = bredsum(eo, red);
    const float sumi = bredsum(ei, red);
    const float suma = bredsum(ea, red);

    const float oa = eo / sumo;
    const float ia = ei / sumi;
    const float aw = ea / suma;
    const float msgv = (j == i) ? ia : (oa + ia);
    g_msg[base + j] = msgv * aw;
}

// ============================================================
// node_hidden
// ============================================================
__global__ void nodeh_kernel()
{
    const int bm = blockIdx.x;
    const int b = bm >> 7, m = bm & 127;
    const int tid = threadIdx.x;
    const int h = tid >> 3;
    const long mbase = (((long)b * HEADS + h) * NB + m) * NB;
    const float4* vp = (const float4*)(g_v + (long)b * NB * DM) + tid;

    float4 acc = make_float4(0.f, 0.f, 0.f, 0.f);
    for (int n = 0; n < NB; n++) {
        const float mv = g_msg[mbase + n];
        const float4 vv = vp[(long)n * (DM / 4)];
        acc.x = fmaf(mv, vv.x, acc.x);
        acc.y = fmaf(mv, vv.y, acc.y);
        acc.z = fmaf(mv, vv.z, acc.z);
        acc.w = fmaf(mv, vv.w, acc.w);
    }
    ((float4*)(g_x + (long)bm * DM))[tid] = acc;
}

// ============================================================
extern "C" void kernel_launch(void* const* d_in, const int* in_sizes, int n_in,
                              void* d_out, int out_size)
{
    const float* query = (const float*)d_in[0];
    const float* value = (const float*)d_in[1];
    const float* kedge = (const float*)d_in[2];
    const float* adjm  = (const float*)d_in[3];
    const int*   mask  = (const int*)  d_in[4];
    const float* Wq = (const float*)d_in[5];
    const float* bq = (const float*)d_in[6];
    const float* Wk = (const float*)d_in[7];
    const float* bk = (const float*)d_in[8];
    const float* Wv = (const float*)d_in[9];
    const float* bv = (const float*)d_in[10];
    const float* Wo = (const float*)d_in[11];
    const float* bo = (const float*)d_in[12];
    const float* We = (const float*)d_in[13];
    const float* be = (const float*)d_in[14];
    const float* lam = (const float*)d_in[15];

    float* x_out = (float*)d_out;
    float* e_out = (float*)d_out + (long)BATCH * NB * DM;

    float *p_k, *p_q, *p_v, *p_msg, *p_x;
    __nv_bfloat16 *p_wkh, *p_wkl, *p_weh, *p_wel;
    cudaGetSymbolAddress((void**)&p_k,   g_k);
    cudaGetSymbolAddress((void**)&p_q,   g_q);
    cudaGetSymbolAddress((void**)&p_v,   g_v);
    cudaGetSymbolAddress((void**)&p_msg, g_msg);
    cudaGetSymbolAddress((void**)&p_x,   g_x);
    cudaGetSymbolAddress((void**)&p_wkh, g_wkh);
    cudaGetSymbolAddress((void**)&p_wkl, g_wkl);
    cudaGetSymbolAddress((void**)&p_weh, g_weh);
    cudaGetSymbolAddress((void**)&p_wel, g_wel);

    cudaFuncSetAttribute(mma_gemm<false>, cudaFuncAttributeMaxDynamicSharedMemorySize, SMTOT);
    cudaFuncSetAttribute(mma_gemm<true>,  cudaFuncAttributeMaxDynamicSharedMemorySize, SMTOT);

    const int Erows = BATCH * NB * NB;       // 131072

    dim3 blk(256);
    dim3 gqv(DM / 64, BATCH * NB / 64, 2);   // (8, 16, 2): q and v batched
    dim3 gx (DM / 64, BATCH * NB / 64, 1);
    dim3 gbig(DM / 128, Erows / 128);        // (4, 1024)

    // weight splits (both in one launch)
    wsplit_kernel<<<dim3(DM * DM / 256, 2), 256>>>(Wk, We);

    // q and v projections in one batched launch
    sgemm64<<<gqv, blk>>>(query, value, Wq, Wv, bq, bv, p_q, p_v);

    // k = key_edge @ Wk + bk  (HMMA split-bf16, warp 64x32, 2 CTA/SM)
    mma_gemm<false><<<gbig, blk, SMTOT>>>(kedge, p_wkh, p_wkl, bk, p_k, nullptr);

    scores_kernel<<<BATCH * NB, 256>>>();
    message_kernel<<<BATCH * HEADS * NB, 128>>>(adjm, mask, lam);
    nodeh_kernel<<<BATCH * NB, 128>>>();

    sgemm64<<<gx, blk>>>(p_x, p_x, Wo, Wo, bo, bo, x_out, x_out);

    // e_out = (msg ⊙ k) @ We + be  (HMMA split-bf16, msg fused on A-load)
    mma_gemm<true><<<gbig, blk, SMTOT>>>(p_k, p_weh, p_wel, be, e_out, p_msg);
}

// round 15
// speedup vs baseline: 1.0650x; 1.0650x over previous
#include <cuda_runtime.h>
#include <cuda_bf16.h>
#include <math.h>
#include <stdint.h>

#define NB     128
#define BATCH  8
#define HEADS  16
#define DM     512
#define DKH    32

// ---- scratch (device globals: no allocation allowed) ----
__device__ float g_k   [(long)BATCH*NB*NB*DM];   // 268 MB: k = key_edge@Wk+bk, layout (b,m,n,d)
__device__ float g_q   [BATCH*NB*DM];
__device__ float g_v   [BATCH*NB*DM];
__device__ float g_outS[BATCH*HEADS*NB*NB];      // out_scores (b,h,m,n)
__device__ float g_inS [BATCH*HEADS*NB*NB];      // in_scores stored transposed: (b,h,n,m)
__device__ float g_msg [BATCH*HEADS*NB*NB];      // message*adj (b,h,m,n)
__device__ float g_x   [BATCH*NB*DM];            // node_hidden (b,m,d)

// split+transposed weights (bf16): W*[n][k] hi/lo
__device__ __nv_bfloat16 g_wkh[DM*DM];
__device__ __nv_bfloat16 g_wkl[DM*DM];
__device__ __nv_bfloat16 g_weh[DM*DM];
__device__ __nv_bfloat16 g_wel[DM*DM];

// ============================================================
// helpers
// ============================================================
__device__ __forceinline__ uint32_t smem_u32(const void* p) {
    uint32_t a;
    asm("{ .reg .u64 t; cvta.to.shared.u64 t, %1; cvt.u32.u64 %0, t; }" : "=r"(a) : "l"(p));
    return a;
}
__device__ __forceinline__ void cp16(uint32_t dst, const void* src) {
    asm volatile("cp.async.cg.shared.global [%0], [%1], 16;" :: "r"(dst), "l"(src) : "memory");
}
#define CP_COMMIT() asm volatile("cp.async.commit_group;" ::: "memory")
#define CP_WAIT0()  asm volatile("cp.async.wait_group 0;" ::: "memory")

#define LDMX4(r, a) \
    asm volatile("ldmatrix.sync.aligned.m8n8.x4.shared.b16 {%0,%1,%2,%3}, [%4];" \
        : "=r"((r)[0]), "=r"((r)[1]), "=r"((r)[2]), "=r"((r)[3]) : "r"(a))

// pack two floats -> bf16x2 (x low half, y high half)
__device__ __forceinline__ uint32_t pack_bf(float x, float y) {
    uint32_t r;
    asm("cvt.rn.bf16x2.f32 %0, %1, %2;" : "=r"(r) : "f"(y), "f"(x));
    return r;
}
__device__ __forceinline__ float bf_hi(float x) {
    return __bfloat162float(__float2bfloat16(x));
}

// m16n8k16 row.col bf16 -> f32 accumulate
__device__ __forceinline__ void mma_bf16(float* d, const uint32_t* a, const uint32_t* b) {
    asm volatile(
        "mma.sync.aligned.m16n8k16.row.col.f32.bf16.bf16.f32 "
        "{%0,%1,%2,%3}, {%4,%5,%6,%7}, {%8,%9}, {%0,%1,%2,%3};"
        : "+f"(d[0]), "+f"(d[1]), "+f"(d[2]), "+f"(d[3])
        : "r"(a[0]), "r"(a[1]), "r"(a[2]), "r"(a[3]), "r"(b[0]), "r"(b[1]));
}

// ============================================================
// Weight prep (both weights in one launch; blockIdx.y selects)
// ============================================================
__global__ void wsplit_kernel(const float* __restrict__ Wk,
                              const float* __restrict__ We)
{
    const float* W = blockIdx.y ? We : Wk;
    __nv_bfloat16* Wh = blockIdx.y ? g_weh : g_wkh;
    __nv_bfloat16* Wl = blockIdx.y ? g_wel : g_wkl;
    int i = blockIdx.x * 256 + threadIdx.x;   // i = k*512 + n
    int k = i >> 9, n = i & 511;
    float x = W[i];
    __nv_bfloat16 h = __float2bfloat16(x);
    float r = x - __bfloat162float(h);
    Wh[n * DM + k] = h;
    Wl[n * DM + k] = __float2bfloat16(r);
}

// ============================================================
// HMMA split-bf16 GEMM: C[M,512] = A[M,512] @ Wt^T + bias
//   CTA tile 128x128, 256 threads (8 warps, 2M x 4N), warp 64x32.
//   k-chunk = 32, double-buffered dynamic smem, ldmatrix.x4,
//   3-term split: Ah*Bh + Ah*Bl + Al*Bh.  2 CTAs/SM.
//   USE_MSG: scale A rows by msg[b, head=c, m, n] (head == k32-chunk idx).
// ============================================================
#define APITCH 80
#define STAGE  (128 * APITCH)       // 10240 B per array
#define SMTOT  (2 * 4 * STAGE)      // 81920 B

template<bool USE_MSG>
__global__ __launch_bounds__(256, 2)
void mma_gemm(const float* __restrict__ A,
              const __nv_bfloat16* __restrict__ Bhp,
              const __nv_bfloat16* __restrict__ Blp,
              const float* __restrict__ bias,
              float* __restrict__ C,
              const float* __restrict__ msg)
{
    extern __shared__ __align__(16) uint8_t dsm[];
    const uint32_t sb = smem_u32(dsm);

    const int tid = threadIdx.x;
    const int wid = tid >> 5, lid = tid & 31;
    const int wm = wid & 1, wn = wid >> 1;
    const int g  = lid >> 2, tg = lid & 3;
    const int n0 = blockIdx.x * 128;
    const long m0 = (long)blockIdx.y * 128;

    // ---- A-load mapping: thread handles row ar, 16 fp32 at (tid&1)*16 ----
    const int ar = tid >> 1, ahalf = tid & 1;
    const long agr = m0 + ar;
    const float* Abase = A + agr * DM + ahalf * 16;
    long msgb = 0;
    if (USE_MSG) msgb = (((agr >> 14) * (long)HEADS) << 14) + (agr & 16383);

    // ---- ldmatrix lane address components ----
    const uint32_t a_lane = (uint32_t)((lid & 15) * APITCH + (lid >> 4) * 16);
    const uint32_t b_lane = (uint32_t)((((lid & 7) + ((lid & 16) ? 8 : 0)) * APITCH) + ((lid & 8) ? 16 : 0));
    const uint32_t a_warp = (uint32_t)(wm * 64 * APITCH);
    const uint32_t b_warp = (uint32_t)(wn * 32 * APITCH);

    float acc[4][4][4];
#pragma unroll
    for (int mi = 0; mi < 4; mi++)
#pragma unroll
        for (int ni = 0; ni < 4; ni++)
#pragma unroll
            for (int r = 0; r < 4; r++) acc[mi][ni][r] = 0.f;

    float areg[16];

    auto LDA = [&](int c) {
        const float* p = Abase + c * 32;
#pragma unroll
        for (int q = 0; q < 4; q++) {
            float4 v = *(const float4*)(p + q * 4);
            areg[q * 4 + 0] = v.x; areg[q * 4 + 1] = v.y;
            areg[q * 4 + 2] = v.z; areg[q * 4 + 3] = v.w;
        }
        if (USE_MSG) {
            float s = msg[msgb + ((long)c << 14)];
#pragma unroll
            for (int i = 0; i < 16; i++) areg[i] *= s;
        }
    };
    auto STA = [&](int s) {
        float h[16];
#pragma unroll
        for (int i = 0; i < 16; i++) h[i] = bf_hi(areg[i]);
        uint32_t ph[8], pl[8];
#pragma unroll
        for (int i = 0; i < 8; i++) {
            ph[i] = pack_bf(h[2*i], h[2*i+1]);
            pl[i] = pack_bf(areg[2*i] - h[2*i], areg[2*i+1] - h[2*i+1]);
        }
        const uint32_t dh = sb + (uint32_t)(s * 4 * STAGE) + (uint32_t)(ar * APITCH + ahalf * 32);
        const uint32_t dl = dh + STAGE;
        asm volatile("st.shared.v4.b32 [%0], {%1,%2,%3,%4};" :: "r"(dh),      "r"(ph[0]), "r"(ph[1]), "r"(ph[2]), "r"(ph[3]) : "memory");
        asm volatile("st.shared.v4.b32 [%0], {%1,%2,%3,%4};" :: "r"(dh + 16), "r"(ph[4]), "r"(ph[5]), "r"(ph[6]), "r"(ph[7]) : "memory");
        asm volatile("st.shared.v4.b32 [%0], {%1,%2,%3,%4};" :: "r"(dl),      "r"(pl[0]), "r"(pl[1]), "r"(pl[2]), "r"(pl[3]) : "memory");
        asm volatile("st.shared.v4.b32 [%0], {%1,%2,%3,%4};" :: "r"(dl + 16), "r"(pl[4]), "r"(pl[5]), "r"(pl[6]), "r"(pl[7]) : "memory");
    };
    auto CPB = [&](int c, int s) {
        const uint32_t db = sb + (uint32_t)(s * 4 * STAGE) + (uint32_t)(2 * STAGE);
#pragma unroll
        for (int q = 0; q < 2; q++) {
            int u = q * 256 + tid;               // 512 16B-units per array
            int row = u >> 2, seg = u & 3;
            uint32_t d = db + (uint32_t)(row * APITCH + seg * 16);
            long so = (long)(n0 + row) * DM + c * 32 + seg * 8;
            cp16(d, Bhp + so);
            cp16(d + STAGE, Blp + so);
        }
    };

    auto COMPUTE = [&](int s) {
        const uint32_t base = sb + (uint32_t)(s * 4 * STAGE);
        const uint32_t pAh = base + a_warp + a_lane;
        const uint32_t pAl = pAh + STAGE;
        const uint32_t pBh = base + (uint32_t)(2 * STAGE) + b_warp + b_lane;
        const uint32_t pBl = pBh + STAGE;
#pragma unroll
        for (int ks = 0; ks < 2; ks++) {
            const uint32_t ko = (uint32_t)(ks * 32);
            uint32_t af[4][4], bh[4][2], bl[4][2];
#pragma unroll
            for (int mi = 0; mi < 4; mi++)
                LDMX4(af[mi], pAh + ko + (uint32_t)(mi * 16 * APITCH));
#pragma unroll
            for (int p = 0; p < 2; p++) {
                uint32_t r[4];
                LDMX4(r, pBh + ko + (uint32_t)(p * 16 * APITCH));
                bh[2*p][0] = r[0]; bh[2*p][1] = r[1];
                bh[2*p+1][0] = r[2]; bh[2*p+1][1] = r[3];
            }
#pragma unroll
            for (int mi = 0; mi < 4; mi++)
#pragma unroll
                for (int ni = 0; ni < 4; ni++) mma_bf16(acc[mi][ni], af[mi], bh[ni]);
#pragma unroll
            for (int p = 0; p < 2; p++) {
                uint32_t r[4];
                LDMX4(r, pBl + ko + (uint32_t)(p * 16 * APITCH));
                bl[2*p][0] = r[0]; bl[2*p][1] = r[1];
                bl[2*p+1][0] = r[2]; bl[2*p+1][1] = r[3];
            }
#pragma unroll
            for (int mi = 0; mi < 4; mi++)
#pragma unroll
                for (int ni = 0; ni < 4; ni++) mma_bf16(acc[mi][ni], af[mi], bl[ni]);
#pragma unroll
            for (int mi = 0; mi < 4; mi++)      // reuse af regs for A-lo
                LDMX4(af[mi], pAl + ko + (uint32_t)(mi * 16 * APITCH));
#pragma unroll
            for (int mi = 0; mi < 4; mi++)
#pragma unroll
                for (int ni = 0; ni < 4; ni++) mma_bf16(acc[mi][ni], af[mi], bh[ni]);
        }
    };

    // ---- pipeline: 16 k32-chunks, double buffered ----
    LDA(0);
    CPB(0, 0); CP_COMMIT();
    STA(0);
    CP_WAIT0(); __syncthreads();
#pragma unroll 1
    for (int c = 0; c < 16; c++) {
        const int s = c & 1;
        const bool more = (c < 15);
        if (more) { CPB(c + 1, s ^ 1); CP_COMMIT(); LDA(c + 1); }
        COMPUTE(s);
        if (more) { STA(s ^ 1); CP_WAIT0(); }
        __syncthreads();
    }

    // ---- epilogue ----
#pragma unroll
    for (int ni = 0; ni < 4; ni++) {
        const int col = n0 + wn * 32 + ni * 8 + tg * 2;
        const float b0 = bias[col], b1 = bias[col + 1];
#pragma unroll
        for (int mi = 0; mi < 4; mi++) {
            const long row = m0 + wm * 64 + mi * 16 + g;
            float2 o0 = make_float2(acc[mi][ni][0] + b0, acc[mi][ni][1] + b1);
            float2 o1 = make_float2(acc[mi][ni][2] + b0, acc[mi][ni][3] + b1);
            *(float2*)(C + row * DM + col)       = o0;
            *(float2*)(C + (row + 8) * DM + col) = o1;
        }
    }
}

// ============================================================
// fp32 SGEMM 64x64 tiles for the small projections (M=1024)
// blockIdx.z selects problem {0,1} so two GEMMs batch in one launch.
// ============================================================
__global__ __launch_bounds__(256)
void sgemm64(const float* __restrict__ A0, const float* __restrict__ A1,
             const float* __restrict__ W0, const float* __restrict__ W1,
             const float* __restrict__ b0p, const float* __restrict__ b1p,
             float* __restrict__ C0, float* __restrict__ C1)
{
    const float* A    = blockIdx.z ? A1 : A0;
    const float* B    = blockIdx.z ? W1 : W0;
    const float* bias = blockIdx.z ? b1p : b0p;
    float*       C    = blockIdx.z ? C1 : C0;

    __shared__ float As[16][64];
    __shared__ float Bs[16][64];

    const int tid = threadIdx.x;
    const int m0 = blockIdx.y * 64, n0 = blockIdx.x * 64;
    const int tx = tid & 15, ty = tid >> 4;

    const int aRow = tid >> 2, aCol = (tid & 3) * 4;
    const int bRow = tid >> 4, bCol = (tid & 15) * 4;

    float acc[4][4];
#pragma unroll
    for (int i = 0; i < 4; i++)
#pragma unroll
        for (int j = 0; j < 4; j++) acc[i][j] = 0.f;

    const float* Ap = A + (long)(m0 + aRow) * DM + aCol;
    const float* Bp = B + (long)bRow * DM + n0 + bCol;

    for (int k0 = 0; k0 < DM; k0 += 16) {
        float4 av = *(const float4*)(Ap + k0);
        As[aCol + 0][aRow] = av.x;
        As[aCol + 1][aRow] = av.y;
        As[aCol + 2][aRow] = av.z;
        As[aCol + 3][aRow] = av.w;
        *(float4*)&Bs[bRow][bCol] = *(const float4*)(Bp + (long)k0 * DM);
        __syncthreads();
#pragma unroll
        for (int kk = 0; kk < 16; kk++) {
            float4 a4 = *(float4*)&As[kk][ty * 4];
            float4 b4 = *(float4*)&Bs[kk][tx * 4];
            float ar[4] = {a4.x, a4.y, a4.z, a4.w};
            float br[4] = {b4.x, b4.y, b4.z, b4.w};
#pragma unroll
            for (int i = 0; i < 4; i++)
#pragma unroll
                for (int j = 0; j < 4; j++) acc[i][j] = fmaf(ar[i], br[j], acc[i][j]);
        }
        __syncthreads();
    }

    const int c = n0 + tx * 4;
    const float4 bz = *(const float4*)&bias[c];
#pragma unroll
    for (int i = 0; i < 4; i++) {
        const long r = m0 + ty * 4 + i;
        float4 o;
        o.x = acc[i][0] + bz.x; o.y = acc[i][1] + bz.y;
        o.z = acc[i][2] + bz.z; o.w = acc[i][3] + bz.w;
        *(float4*)&C[r * DM + c] = o;
    }
}

// ============================================================
// Scores (v1 structure, n-split for occupancy):
// grid (b*m, 4), block 128.  Block handles n in [32*ys, 32*ys+32).
//   outS[b,h,m,n] = q(b,m) . k(b,m,n)   (8 threads per head)
//   inS [b,h,n,m] = q(b,n) . k(b,m,n)
// ============================================================
__global__ void scores_kernel()
{
    const int bm = blockIdx.x;
    const int b  = bm >> 7, m = bm & 127;
    const int n_lo = blockIdx.y * 32;
    const int tid = threadIdx.x;
    __shared__ float qm[DM];

    ((float4*)qm)[tid] = ((const float4*)(g_q + (long)bm * DM))[tid];
    __syncthreads();
    const float4 q4 = ((float4*)qm)[tid];
    const int h = tid >> 3;
    const float scale = 0.17677669529663687f;

    const float4* krow0 = (const float4*)(g_k + (long)bm * NB * DM) + tid;
    const float4* qb    = (const float4*)(g_q + (long)b * NB * DM) + tid;

    for (int n = n_lo; n < n_lo + 32; n++) {
        const float4 k4  = krow0[(long)n * (DM / 4)];
        const float4 qn4 = qb[(long)n * (DM / 4)];
        float po = k4.x*q4.x  + k4.y*q4.y  + k4.z*q4.z  + k4.w*q4.w;
        float pi = k4.x*qn4.x + k4.y*qn4.y + k4.z*qn4.z + k4.w*qn4.w;
#pragma unroll
        for (int o = 4; o; o >>= 1) {
            po += __shfl_xor_sync(0xffffffffu, po, o);
            pi += __shfl_xor_sync(0xffffffffu, pi, o);
        }
        if ((tid & 7) == 0) {
            g_outS[(((long)b*HEADS + h)*NB + m)*NB + n] = po * scale;
            g_inS [(((long)b*HEADS + h)*NB + n)*NB + m] = pi * scale;
        }
    }
}

// ============================================================
// Softmax + message + adj weighting.
// ============================================================
__device__ __forceinline__ float bredmax(float v, float* sm)
{
#pragma unroll
    for (int o = 16; o; o >>= 1) v = fmaxf(v, __shfl_xor_sync(0xffffffffu, v, o));
    if ((threadIdx.x & 31) == 0) sm[threadIdx.x >> 5] = v;
    __syncthreads();
    float r = fmaxf(fmaxf(sm[0], sm[1]), fmaxf(sm[2], sm[3]));
    __syncthreads();
    return r;
}
__device__ __forceinline__ float bredsum(float v, float* sm)
{
#pragma unroll
    for (int o = 16; o; o >>= 1) v += __shfl_xor_sync(0xffffffffu, v, o);
    if ((threadIdx.x & 31) == 0) sm[threadIdx.x >> 5] = v;
    __syncthreads();
    float r = sm[0] + sm[1] + sm[2] + sm[3];
    __syncthreads();
    return r;
}

__global__ void message_kernel(const float* __restrict__ adjm,
                               const int* __restrict__ mask,
                               const float* __restrict__ lam_p)
{
    const long row = blockIdx.x;
    const int i  = row & 127;
    const int b  = (int)(row >> 11);
    const int j  = threadIdx.x;
    const float lam = *lam_p;
    __shared__ float red[4];

    const int mk = mask[b * NB + j];
    const long base = row * NB;
    float so = g_outS[base + j];
    float si = g_inS [base + j];
    float aj = -lam * adjm[((long)b * NB + i) * NB + j];
    const float NEG = -3.0e38f;
    if (mk == 0) { so = NEG; si = NEG; aj = NEG; }

    const float mo = bredmax(so, red);
    const float mi = bredmax(si, red);
    const float ma = bredmax(aj, red);
    const float eo = (mk == 0) ? 0.f : expf(so - mo);
    const float ei = (mk == 0) ? 0.f : expf(si - mi);
    const float ea = (mk == 0) ? 0.f : expf(aj - ma);
    const float sumo = bredsum(eo, red);
    const float sumi = bredsum(ei, red);
    const float suma = bredsum(ea, red);

    const float oa = eo / sumo;
    const float ia = ei / sumi;
    const float aw = ea / suma;
    const float msgv = (j == i) ? ia : (oa + ia);
    g_msg[base + j] = msgv * aw;
}

// ============================================================
// node_hidden
// ============================================================
__global__ void nodeh_kernel()
{
    const int bm = blockIdx.x;
    const int b = bm >> 7, m = bm & 127;
    const int tid = threadIdx.x;
    const int h = tid >> 3;
    const long mbase = (((long)b * HEADS + h) * NB + m) * NB;
    const float4* vp = (const float4*)(g_v + (long)b * NB * DM) + tid;

    float4 acc = make_float4(0.f, 0.f, 0.f, 0.f);
    for (int n = 0; n < NB; n++) {
        const float mv = g_msg[mbase + n];
        const float4 vv = vp[(long)n * (DM / 4)];
        acc.x = fmaf(mv, vv.x, acc.x);
        acc.y = fmaf(mv, vv.y, acc.y);
        acc.z = fmaf(mv, vv.z, acc.z);
        acc.w = fmaf(mv, vv.w, acc.w);
    }
    ((float4*)(g_x + (long)bm * DM))[tid] = acc;
}

// ============================================================
extern "C" void kernel_launch(void* const* d_in, const int* in_sizes, int n_in,
                              void* d_out, int out_size)
{
    const float* query = (const float*)d_in[0];
    const float* value = (const float*)d_in[1];
    const float* kedge = (const float*)d_in[2];
    const float* adjm  = (const float*)d_in[3];
    const int*   mask  = (const int*)  d_in[4];
    const float* Wq = (const float*)d_in[5];
    const float* bq = (const float*)d_in[6];
    const float* Wk = (const float*)d_in[7];
    const float* bk = (const float*)d_in[8];
    const float* Wv = (const float*)d_in[9];
    const float* bv = (const float*)d_in[10];
    const float* Wo = (const float*)d_in[11];
    const float* bo = (const float*)d_in[12];
    const float* We = (const float*)d_in[13];
    const float* be = (const float*)d_in[14];
    const float* lam = (const float*)d_in[15];

    float* x_out = (float*)d_out;
    float* e_out = (float*)d_out + (long)BATCH * NB * DM;

    float *p_k, *p_q, *p_v, *p_msg, *p_x;
    __nv_bfloat16 *p_wkh, *p_wkl, *p_weh, *p_wel;
    cudaGetSymbolAddress((void**)&p_k,   g_k);
    cudaGetSymbolAddress((void**)&p_q,   g_q);
    cudaGetSymbolAddress((void**)&p_v,   g_v);
    cudaGetSymbolAddress((void**)&p_msg, g_msg);
    cudaGetSymbolAddress((void**)&p_x,   g_x);
    cudaGetSymbolAddress((void**)&p_wkh, g_wkh);
    cudaGetSymbolAddress((void**)&p_wkl, g_wkl);
    cudaGetSymbolAddress((void**)&p_weh, g_weh);
    cudaGetSymbolAddress((void**)&p_wel, g_wel);

    cudaFuncSetAttribute(mma_gemm<false>, cudaFuncAttributeMaxDynamicSharedMemorySize, SMTOT);
    cudaFuncSetAttribute(mma_gemm<true>,  cudaFuncAttributeMaxDynamicSharedMemorySize, SMTOT);

    const int Erows = BATCH * NB * NB;       // 131072

    dim3 blk(256);
    dim3 gqv(DM / 64, BATCH * NB / 64, 2);   // (8, 16, 2): q and v batched
    dim3 gx (DM / 64, BATCH * NB / 64, 1);
    dim3 gbig(DM / 128, Erows / 128);        // (4, 1024)

    // weight splits (both in one launch)
    wsplit_kernel<<<dim3(DM * DM / 256, 2), 256>>>(Wk, We);

    // q and v projections in one batched launch
    sgemm64<<<gqv, blk>>>(query, value, Wq, Wv, bq, bv, p_q, p_v);

    // k = key_edge @ Wk + bk  (HMMA split-bf16, warp 64x32, 2 CTA/SM)
    mma_gemm<false><<<gbig, blk, SMTOT>>>(kedge, p_wkh, p_wkl, bk, p_k, nullptr);

    // scores: n-split x4 for occupancy
    scores_kernel<<<dim3(BATCH * NB, 4), 128>>>();
    message_kernel<<<BATCH * HEADS * NB, 128>>>(adjm, mask, lam);
    nodeh_kernel<<<BATCH * NB, 128>>>();

    sgemm64<<<gx, blk>>>(p_x, p_x, Wo, Wo, bo, bo, x_out, x_out);

    // e_out = (msg ⊙ k) @ We + be  (HMMA split-bf16, msg fused on A-load)
    mma_gemm<true><<<gbig, blk, SMTOT>>>(p_k, p_weh, p_wel, be, e_out, p_msg);
}

// round 16
// speedup vs baseline: 1.1738x; 1.1021x over previous
#include <cuda_runtime.h>
#include <cuda_bf16.h>
#include <cuda_fp16.h>
#include <math.h>
#include <stdint.h>

#define NB     128
#define BATCH  8
#define HEADS  16
#define DM     512
#define DKH    32

// ---- scratch (device globals: no allocation allowed) ----
__device__ float g_k   [(long)BATCH*NB*NB*DM];   // 268 MB: k = key_edge@Wk+bk, layout (b,m,n,d)
__device__ float g_q   [BATCH*NB*DM];
__device__ float g_v   [BATCH*NB*DM];
__device__ float g_outS[BATCH*HEADS*NB*NB];      // out_scores (b,h,m,n)
__device__ float g_inS [BATCH*HEADS*NB*NB];      // in_scores stored transposed: (b,h,n,m)
__device__ float g_msg [BATCH*HEADS*NB*NB];      // message*adj (b,h,m,n)
__device__ float g_x   [BATCH*NB*DM];            // node_hidden (b,m,d)

// split+transposed weights: Wk as bf16 hi/lo (GEMM1), We as fp16 hi/lo (GEMM2)
__device__ __nv_bfloat16 g_wkh[DM*DM];
__device__ __nv_bfloat16 g_wkl[DM*DM];
__device__ __half        g_weh16[DM*DM];
__device__ __half        g_wel16[DM*DM];

// ============================================================
// helpers
// ============================================================
__device__ __forceinline__ uint32_t smem_u32(const void* p) {
    uint32_t a;
    asm("{ .reg .u64 t; cvta.to.shared.u64 t, %1; cvt.u32.u64 %0, t; }" : "=r"(a) : "l"(p));
    return a;
}
__device__ __forceinline__ void cp16(uint32_t dst, const void* src) {
    asm volatile("cp.async.cg.shared.global [%0], [%1], 16;" :: "r"(dst), "l"(src) : "memory");
}
#define CP_COMMIT() asm volatile("cp.async.commit_group;" ::: "memory")
#define CP_WAIT0()  asm volatile("cp.async.wait_group 0;" ::: "memory")

#define LDMX4(r, a) \
    asm volatile("ldmatrix.sync.aligned.m8n8.x4.shared.b16 {%0,%1,%2,%3}, [%4];" \
        : "=r"((r)[0]), "=r"((r)[1]), "=r"((r)[2]), "=r"((r)[3]) : "r"(a))

// pack two floats -> bf16x2 / f16x2 (x low half, y high half)
__device__ __forceinline__ uint32_t pack_bf(float x, float y) {
    uint32_t r;
    asm("cvt.rn.bf16x2.f32 %0, %1, %2;" : "=r"(r) : "f"(y), "f"(x));
    return r;
}
__device__ __forceinline__ uint32_t pack_f16(float x, float y) {
    uint32_t r;
    asm("cvt.rn.f16x2.f32 %0, %1, %2;" : "=r"(r) : "f"(y), "f"(x));
    return r;
}
__device__ __forceinline__ float bf_hi(float x) {
    return __bfloat162float(__float2bfloat16(x));
}

// m16n8k16 row.col -> f32 accumulate
__device__ __forceinline__ void mma_bf16(float* d, const uint32_t* a, const uint32_t* b) {
    asm volatile(
        "mma.sync.aligned.m16n8k16.row.col.f32.bf16.bf16.f32 "
        "{%0,%1,%2,%3}, {%4,%5,%6,%7}, {%8,%9}, {%0,%1,%2,%3};"
        : "+f"(d[0]), "+f"(d[1]), "+f"(d[2]), "+f"(d[3])
        : "r"(a[0]), "r"(a[1]), "r"(a[2]), "r"(a[3]), "r"(b[0]), "r"(b[1]));
}
__device__ __forceinline__ void mma_f16(float* d, const uint32_t* a, const uint32_t* b) {
    asm volatile(
        "mma.sync.aligned.m16n8k16.row.col.f32.f16.f16.f32 "
        "{%0,%1,%2,%3}, {%4,%5,%6,%7}, {%8,%9}, {%0,%1,%2,%3};"
        : "+f"(d[0]), "+f"(d[1]), "+f"(d[2]), "+f"(d[3])
        : "r"(a[0]), "r"(a[1]), "r"(a[2]), "r"(a[3]), "r"(b[0]), "r"(b[1]));
}

// ============================================================
// Weight prep (both weights in one launch; blockIdx.y selects)
//   y=0: Wk -> bf16 hi/lo (transposed)   y=1: We -> fp16 hi/lo
// ============================================================
__global__ void wsplit_kernel(const float* __restrict__ Wk,
                              const float* __restrict__ We)
{
    int i = blockIdx.x * 256 + threadIdx.x;   // i = k*512 + n
    int k = i >> 9, n = i & 511;
    if (blockIdx.y == 0) {
        float x = Wk[i];
        __nv_bfloat16 h = __float2bfloat16(x);
        float r = x - __bfloat162float(h);
        g_wkh[n * DM + k] = h;
        g_wkl[n * DM + k] = __float2bfloat16(r);
    } else {
        float x = We[i];
        __half h = __float2half(x);
        float r = x - __half2float(h);
        g_weh16[n * DM + k] = h;
        g_wel16[n * DM + k] = __float2half(r);
    }
}

// ============================================================
// GEMM1: HMMA split-bf16 (3-term), CTA 128x128, warp 64x32, 2 CTA/SM
// ============================================================
#define APITCH 80
#define STAGE  (128 * APITCH)       // 10240 B per array
#define SMTOT  (2 * 4 * STAGE)      // 81920 B

__global__ __launch_bounds__(256, 2)
void mma_gemm(const float* __restrict__ A,
              const __nv_bfloat16* __restrict__ Bhp,
              const __nv_bfloat16* __restrict__ Blp,
              const float* __restrict__ bias,
              float* __restrict__ C)
{
    extern __shared__ __align__(16) uint8_t dsm[];
    const uint32_t sb = smem_u32(dsm);

    const int tid = threadIdx.x;
    const int wid = tid >> 5, lid = tid & 31;
    const int wm = wid & 1, wn = wid >> 1;
    const int g  = lid >> 2, tg = lid & 3;
    const int n0 = blockIdx.x * 128;
    const long m0 = (long)blockIdx.y * 128;

    const int ar = tid >> 1, ahalf = tid & 1;
    const long agr = m0 + ar;
    const float* Abase = A + agr * DM + ahalf * 16;

    const uint32_t a_lane = (uint32_t)((lid & 15) * APITCH + (lid >> 4) * 16);
    const uint32_t b_lane = (uint32_t)((((lid & 7) + ((lid & 16) ? 8 : 0)) * APITCH) + ((lid & 8) ? 16 : 0));
    const uint32_t a_warp = (uint32_t)(wm * 64 * APITCH);
    const uint32_t b_warp = (uint32_t)(wn * 32 * APITCH);

    float acc[4][4][4];
#pragma unroll
    for (int mi = 0; mi < 4; mi++)
#pragma unroll
        for (int ni = 0; ni < 4; ni++)
#pragma unroll
            for (int r = 0; r < 4; r++) acc[mi][ni][r] = 0.f;

    float areg[16];

    auto LDA = [&](int c) {
        const float* p = Abase + c * 32;
#pragma unroll
        for (int q = 0; q < 4; q++) {
            float4 v = *(const float4*)(p + q * 4);
            areg[q * 4 + 0] = v.x; areg[q * 4 + 1] = v.y;
            areg[q * 4 + 2] = v.z; areg[q * 4 + 3] = v.w;
        }
    };
    auto STA = [&](int s) {
        float h[16];
#pragma unroll
        for (int i = 0; i < 16; i++) h[i] = bf_hi(areg[i]);
        uint32_t ph[8], pl[8];
#pragma unroll
        for (int i = 0; i < 8; i++) {
            ph[i] = pack_bf(h[2*i], h[2*i+1]);
            pl[i] = pack_bf(areg[2*i] - h[2*i], areg[2*i+1] - h[2*i+1]);
        }
        const uint32_t dh = sb + (uint32_t)(s * 4 * STAGE) + (uint32_t)(ar * APITCH + ahalf * 32);
        const uint32_t dl = dh + STAGE;
        asm volatile("st.shared.v4.b32 [%0], {%1,%2,%3,%4};" :: "r"(dh),      "r"(ph[0]), "r"(ph[1]), "r"(ph[2]), "r"(ph[3]) : "memory");
        asm volatile("st.shared.v4.b32 [%0], {%1,%2,%3,%4};" :: "r"(dh + 16), "r"(ph[4]), "r"(ph[5]), "r"(ph[6]), "r"(ph[7]) : "memory");
        asm volatile("st.shared.v4.b32 [%0], {%1,%2,%3,%4};" :: "r"(dl),      "r"(pl[0]), "r"(pl[1]), "r"(pl[2]), "r"(pl[3]) : "memory");
        asm volatile("st.shared.v4.b32 [%0], {%1,%2,%3,%4};" :: "r"(dl + 16), "r"(pl[4]), "r"(pl[5]), "r"(pl[6]), "r"(pl[7]) : "memory");
    };
    auto CPB = [&](int c, int s) {
        const uint32_t db = sb + (uint32_t)(s * 4 * STAGE) + (uint32_t)(2 * STAGE);
#pragma unroll
        for (int q = 0; q < 2; q++) {
            int u = q * 256 + tid;
            int row = u >> 2, seg = u & 3;
            uint32_t d = db + (uint32_t)(row * APITCH + seg * 16);
            long so = (long)(n0 + row) * DM + c * 32 + seg * 8;
            cp16(d, Bhp + so);
            cp16(d + STAGE, Blp + so);
        }
    };

    auto COMPUTE = [&](int s) {
        const uint32_t base = sb + (uint32_t)(s * 4 * STAGE);
        const uint32_t pAh = base + a_warp + a_lane;
        const uint32_t pAl = pAh + STAGE;
        const uint32_t pBh = base + (uint32_t)(2 * STAGE) + b_warp + b_lane;
        const uint32_t pBl = pBh + STAGE;
#pragma unroll
        for (int ks = 0; ks < 2; ks++) {
            const uint32_t ko = (uint32_t)(ks * 32);
            uint32_t af[4][4], bh[4][2], bl[4][2];
#pragma unroll
            for (int mi = 0; mi < 4; mi++)
                LDMX4(af[mi], pAh + ko + (uint32_t)(mi * 16 * APITCH));
#pragma unroll
            for (int p = 0; p < 2; p++) {
                uint32_t r[4];
                LDMX4(r, pBh + ko + (uint32_t)(p * 16 * APITCH));
                bh[2*p][0] = r[0]; bh[2*p][1] = r[1];
                bh[2*p+1][0] = r[2]; bh[2*p+1][1] = r[3];
            }
#pragma unroll
            for (int mi = 0; mi < 4; mi++)
#pragma unroll
                for (int ni = 0; ni < 4; ni++) mma_bf16(acc[mi][ni], af[mi], bh[ni]);
#pragma unroll
            for (int p = 0; p < 2; p++) {
                uint32_t r[4];
                LDMX4(r, pBl + ko + (uint32_t)(p * 16 * APITCH));
                bl[2*p][0] = r[0]; bl[2*p][1] = r[1];
                bl[2*p+1][0] = r[2]; bl[2*p+1][1] = r[3];
            }
#pragma unroll
            for (int mi = 0; mi < 4; mi++)
#pragma unroll
                for (int ni = 0; ni < 4; ni++) mma_bf16(acc[mi][ni], af[mi], bl[ni]);
#pragma unroll
            for (int mi = 0; mi < 4; mi++)
                LDMX4(af[mi], pAl + ko + (uint32_t)(mi * 16 * APITCH));
#pragma unroll
            for (int mi = 0; mi < 4; mi++)
#pragma unroll
                for (int ni = 0; ni < 4; ni++) mma_bf16(acc[mi][ni], af[mi], bh[ni]);
        }
    };

    LDA(0);
    CPB(0, 0); CP_COMMIT();
    STA(0);
    CP_WAIT0(); __syncthreads();
#pragma unroll 1
    for (int c = 0; c < 16; c++) {
        const int s = c & 1;
        const bool more = (c < 15);
        if (more) { CPB(c + 1, s ^ 1); CP_COMMIT(); LDA(c + 1); }
        COMPUTE(s);
        if (more) { STA(s ^ 1); CP_WAIT0(); }
        __syncthreads();
    }

#pragma unroll
    for (int ni = 0; ni < 4; ni++) {
        const int col = n0 + wn * 32 + ni * 8 + tg * 2;
        const float b0 = bias[col], b1 = bias[col + 1];
#pragma unroll
        for (int mi = 0; mi < 4; mi++) {
            const long row = m0 + wm * 64 + mi * 16 + g;
            float2 o0 = make_float2(acc[mi][ni][0] + b0, acc[mi][ni][1] + b1);
            float2 o1 = make_float2(acc[mi][ni][2] + b0, acc[mi][ni][3] + b1);
            *(float2*)(C + row * DM + col)       = o0;
            *(float2*)(C + (row + 8) * DM + col) = o1;
        }
    }
}

// ============================================================
// GEMM2: 2-term fp16.  A = (msg ⊙ k) * 1024 as single fp16;
// B = We split fp16 hi/lo.  acc * (1/1024) + bias in epilogue.
// Per k32 chunk per warp: 64 MMA (was 96), 16 ldmatrix (was 24).
// ============================================================
#define SMTOT2 (2 * 3 * STAGE)      // 61440 B

__global__ __launch_bounds__(256, 2)
void mma_gemm_f16(const float* __restrict__ A,
                  const __half* __restrict__ Bhp,
                  const __half* __restrict__ Blp,
                  const float* __restrict__ bias,
                  float* __restrict__ C,
                  const float* __restrict__ msg)
{
    extern __shared__ __align__(16) uint8_t dsm[];
    const uint32_t sb = smem_u32(dsm);

    const int tid = threadIdx.x;
    const int wid = tid >> 5, lid = tid & 31;
    const int wm = wid & 1, wn = wid >> 1;
    const int g  = lid >> 2, tg = lid & 3;
    const int n0 = blockIdx.x * 128;
    const long m0 = (long)blockIdx.y * 128;

    const int ar = tid >> 1, ahalf = tid & 1;
    const long agr = m0 + ar;
    const float* Abase = A + agr * DM + ahalf * 16;
    const long msgb = (((agr >> 14) * (long)HEADS) << 14) + (agr & 16383);

    const uint32_t a_lane = (uint32_t)((lid & 15) * APITCH + (lid >> 4) * 16);
    const uint32_t b_lane = (uint32_t)((((lid & 7) + ((lid & 16) ? 8 : 0)) * APITCH) + ((lid & 8) ? 16 : 0));
    const uint32_t a_warp = (uint32_t)(wm * 64 * APITCH);
    const uint32_t b_warp = (uint32_t)(wn * 32 * APITCH);

    float acc[4][4][4];
#pragma unroll
    for (int mi = 0; mi < 4; mi++)
#pragma unroll
        for (int ni = 0; ni < 4; ni++)
#pragma unroll
            for (int r = 0; r < 4; r++) acc[mi][ni][r] = 0.f;

    float areg[16];

    auto LDA = [&](int c) {
        const float* p = Abase + c * 32;
#pragma unroll
        for (int q = 0; q < 4; q++) {
            float4 v = *(const float4*)(p + q * 4);
            areg[q * 4 + 0] = v.x; areg[q * 4 + 1] = v.y;
            areg[q * 4 + 2] = v.z; areg[q * 4 + 3] = v.w;
        }
        const float s = msg[msgb + ((long)c << 14)] * 1024.f;  // fp16-normal range
#pragma unroll
        for (int i = 0; i < 16; i++) areg[i] *= s;
    };
    auto STA = [&](int s) {
        uint32_t ph[8];
#pragma unroll
        for (int i = 0; i < 8; i++) ph[i] = pack_f16(areg[2*i], areg[2*i+1]);
        const uint32_t dh = sb + (uint32_t)(s * 3 * STAGE) + (uint32_t)(ar * APITCH + ahalf * 32);
        asm volatile("st.shared.v4.b32 [%0], {%1,%2,%3,%4};" :: "r"(dh),      "r"(ph[0]), "r"(ph[1]), "r"(ph[2]), "r"(ph[3]) : "memory");
        asm volatile("st.shared.v4.b32 [%0], {%1,%2,%3,%4};" :: "r"(dh + 16), "r"(ph[4]), "r"(ph[5]), "r"(ph[6]), "r"(ph[7]) : "memory");
    };
    auto CPB = [&](int c, int s) {
        const uint32_t db = sb + (uint32_t)(s * 3 * STAGE) + (uint32_t)STAGE;
#pragma unroll
        for (int q = 0; q < 2; q++) {
            int u = q * 256 + tid;
            int row = u >> 2, seg = u & 3;
            uint32_t d = db + (uint32_t)(row * APITCH + seg * 16);
            long so = (long)(n0 + row) * DM + c * 32 + seg * 8;
            cp16(d, Bhp + so);
            cp16(d + STAGE, Blp + so);
        }
    };

    auto COMPUTE = [&](int s) {
        const uint32_t base = sb + (uint32_t)(s * 3 * STAGE);
        const uint32_t pA  = base + a_warp + a_lane;
        const uint32_t pBh = base + (uint32_t)STAGE + b_warp + b_lane;
        const uint32_t pBl = pBh + (uint32_t)STAGE;
#pragma unroll
        for (int ks = 0; ks < 2; ks++) {
            const uint32_t ko = (uint32_t)(ks * 32);
            uint32_t af[4][4], bh[4][2];
#pragma unroll
            for (int mi = 0; mi < 4; mi++)
                LDMX4(af[mi], pA + ko + (uint32_t)(mi * 16 * APITCH));
#pragma unroll
            for (int p = 0; p < 2; p++) {
                uint32_t r[4];
                LDMX4(r, pBh + ko + (uint32_t)(p * 16 * APITCH));
                bh[2*p][0] = r[0]; bh[2*p][1] = r[1];
                bh[2*p+1][0] = r[2]; bh[2*p+1][1] = r[3];
            }
#pragma unroll
            for (int mi = 0; mi < 4; mi++)
#pragma unroll
                for (int ni = 0; ni < 4; ni++) mma_f16(acc[mi][ni], af[mi], bh[ni]);
#pragma unroll
            for (int p = 0; p < 2; p++) {
                uint32_t r[4];
                LDMX4(r, pBl + ko + (uint32_t)(p * 16 * APITCH));
                bh[2*p][0] = r[0]; bh[2*p][1] = r[1];
                bh[2*p+1][0] = r[2]; bh[2*p+1][1] = r[3];
            }
#pragma unroll
            for (int mi = 0; mi < 4; mi++)
#pragma unroll
                for (int ni = 0; ni < 4; ni++) mma_f16(acc[mi][ni], af[mi], bh[ni]);
        }
    };

    LDA(0);
    CPB(0, 0); CP_COMMIT();
    STA(0);
    CP_WAIT0(); __syncthreads();
#pragma unroll 1
    for (int c = 0; c < 16; c++) {
        const int s = c & 1;
        const bool more = (c < 15);
        if (more) { CPB(c + 1, s ^ 1); CP_COMMIT(); LDA(c + 1); }
        COMPUTE(s);
        if (more) { STA(s ^ 1); CP_WAIT0(); }
        __syncthreads();
    }

    const float inv = 1.f / 1024.f;
#pragma unroll
    for (int ni = 0; ni < 4; ni++) {
        const int col = n0 + wn * 32 + ni * 8 + tg * 2;
        const float b0 = bias[col], b1 = bias[col + 1];
#pragma unroll
        for (int mi = 0; mi < 4; mi++) {
            const long row = m0 + wm * 64 + mi * 16 + g;
            float2 o0 = make_float2(acc[mi][ni][0] * inv + b0, acc[mi][ni][1] * inv + b1);
            float2 o1 = make_float2(acc[mi][ni][2] * inv + b0, acc[mi][ni][3] * inv + b1);
            *(float2*)(C + row * DM + col)       = o0;
            *(float2*)(C + (row + 8) * DM + col) = o1;
        }
    }
}

// ============================================================
// fp32 SGEMM 64x64 tiles for the small projections (M=1024)
// ============================================================
__global__ __launch_bounds__(256)
void sgemm64(const float* __restrict__ A0, const float* __restrict__ A1,
             const float* __restrict__ W0, const float* __restrict__ W1,
             const float* __restrict__ b0p, const float* __restrict__ b1p,
             float* __restrict__ C0, float* __restrict__ C1)
{
    const float* A    = blockIdx.z ? A1 : A0;
    const float* B    = blockIdx.z ? W1 : W0;
    const float* bias = blockIdx.z ? b1p : b0p;
    float*       C    = blockIdx.z ? C1 : C0;

    __shared__ float As[16][64];
    __shared__ float Bs[16][64];

    const int tid = threadIdx.x;
    const int m0 = blockIdx.y * 64, n0 = blockIdx.x * 64;
    const int tx = tid & 15, ty = tid >> 4;

    const int aRow = tid >> 2, aCol = (tid & 3) * 4;
    const int bRow = tid >> 4, bCol = (tid & 15) * 4;

    float acc[4][4];
#pragma unroll
    for (int i = 0; i < 4; i++)
#pragma unroll
        for (int j = 0; j < 4; j++) acc[i][j] = 0.f;

    const float* Ap = A + (long)(m0 + aRow) * DM + aCol;
    const float* Bp = B + (long)bRow * DM + n0 + bCol;

    for (int k0 = 0; k0 < DM; k0 += 16) {
        float4 av = *(const float4*)(Ap + k0);
        As[aCol + 0][aRow] = av.x;
        As[aCol + 1][aRow] = av.y;
        As[aCol + 2][aRow] = av.z;
        As[aCol + 3][aRow] = av.w;
        *(float4*)&Bs[bRow][bCol] = *(const float4*)(Bp + (long)k0 * DM);
        __syncthreads();
#pragma unroll
        for (int kk = 0; kk < 16; kk++) {
            float4 a4 = *(float4*)&As[kk][ty * 4];
            float4 b4 = *(float4*)&Bs[kk][tx * 4];
            float ar[4] = {a4.x, a4.y, a4.z, a4.w};
            float br[4] = {b4.x, b4.y, b4.z, b4.w};
#pragma unroll
            for (int i = 0; i < 4; i++)
#pragma unroll
                for (int j = 0; j < 4; j++) acc[i][j] = fmaf(ar[i], br[j], acc[i][j]);
        }
        __syncthreads();
    }

    const int c = n0 + tx * 4;
    const float4 bz = *(const float4*)&bias[c];
#pragma unroll
    for (int i = 0; i < 4; i++) {
        const long r = m0 + ty * 4 + i;
        float4 o;
        o.x = acc[i][0] + bz.x; o.y = acc[i][1] + bz.y;
        o.z = acc[i][2] + bz.z; o.w = acc[i][3] + bz.w;
        *(float4*)&C[r * DM + c] = o;
    }
}

// ============================================================
// Scores (n-split x4 for occupancy)
// ============================================================
__global__ void scores_kernel()
{
    const int bm = blockIdx.x;
    const int b  = bm >> 7, m = bm & 127;
    const int n_lo = blockIdx.y * 32;
    const int tid = threadIdx.x;
    __shared__ float qm[DM];

    ((float4*)qm)[tid] = ((const float4*)(g_q + (long)bm * DM))[tid];
    __syncthreads();
    const float4 q4 = ((float4*)qm)[tid];
    const int h = tid >> 3;
    const float scale = 0.17677669529663687f;

    const float4* krow0 = (const float4*)(g_k + (long)bm * NB * DM) + tid;
    const float4* qb    = (const float4*)(g_q + (long)b * NB * DM) + tid;

    for (int n = n_lo; n < n_lo + 32; n++) {
        const float4 k4  = krow0[(long)n * (DM / 4)];
        const float4 qn4 = qb[(long)n * (DM / 4)];
        float po = k4.x*q4.x  + k4.y*q4.y  + k4.z*q4.z  + k4.w*q4.w;
        float pi = k4.x*qn4.x + k4.y*qn4.y + k4.z*qn4.z + k4.w*qn4.w;
#pragma unroll
        for (int o = 4; o; o >>= 1) {
            po += __shfl_xor_sync(0xffffffffu, po, o);
            pi += __shfl_xor_sync(0xffffffffu, pi, o);
        }
        if ((tid & 7) == 0) {
            g_outS[(((long)b*HEADS + h)*NB + m)*NB + n] = po * scale;
            g_inS [(((long)b*HEADS + h)*NB + n)*NB + m] = pi * scale;
        }
    }
}

// ============================================================
// Softmax + message + adj weighting.
// ============================================================
__device__ __forceinline__ float bredmax(float v, float* sm)
{
#pragma unroll
    for (int o = 16; o; o >>= 1) v = fmaxf(v, __shfl_xor_sync(0xffffffffu, v, o));
    if ((threadIdx.x & 31) == 0) sm[threadIdx.x >> 5] = v;
    __syncthreads();
    float r = fmaxf(fmaxf(sm[0], sm[1]), fmaxf(sm[2], sm[3]));
    __syncthreads();
    return r;
}
__device__ __forceinline__ float bredsum(float v, float* sm)
{
#pragma unroll
    for (int o = 16; o; o >>= 1) v += __shfl_xor_sync(0xffffffffu, v, o);
    if ((threadIdx.x & 31) == 0) sm[threadIdx.x >> 5] = v;
    __syncthreads();
    float r = sm[0] + sm[1] + sm[2] + sm[3];
    __syncthreads();
    return r;
}

__global__ void message_kernel(const float* __restrict__ adjm,
                               const int* __restrict__ mask,
                               const float* __restrict__ lam_p)
{
    const long row = blockIdx.x;
    const int i  = row & 127;
    const int b  = (int)(row >> 11);
    const int j  = threadIdx.x;
    const float lam = *lam_p;
    __shared__ float red[4];

    const int mk = mask[b * NB + j];
    const long base = row * NB;
    float so = g_outS[base + j];
    float si = g_inS [base + j];
    float aj = -lam * adjm[((long)b * NB + i) * NB + j];
    const float NEG = -3.0e38f;
    if (mk == 0) { so = NEG; si = NEG; aj = NEG; }

    const float mo = bredmax(so, red);
    const float mi = bredmax(si, red);
    const float ma = bredmax(aj, red);
    const float eo = (mk == 0) ? 0.f : expf(so - mo);
    const float ei = (mk == 0) ? 0.f : expf(si - mi);
    const float ea = (mk == 0) ? 0.f : expf(aj - ma);
    const float sumo = bredsum(eo, red);
    const float sumi = bredsum(ei, red);
    const float suma = bredsum(ea, red);

    const float oa = eo / sumo;
    const float ia = ei / sumi;
    const float aw = ea / suma;
    const float msgv = (j == i) ? ia : (oa + ia);
    g_msg[base + j] = msgv * aw;
}

// ============================================================
// node_hidden
// ============================================================
__global__ void nodeh_kernel()
{
    const int bm = blockIdx.x;
    const int b = bm >> 7, m = bm & 127;
    const int tid = threadIdx.x;
    const int h = tid >> 3;
    const long mbase = (((long)b * HEADS + h) * NB + m) * NB;
    const float4* vp = (const float4*)(g_v + (long)b * NB * DM) + tid;

    float4 acc = make_float4(0.f, 0.f, 0.f, 0.f);
    for (int n = 0; n < NB; n++) {
        const float mv = g_msg[mbase + n];
        const float4 vv = vp[(long)n * (DM / 4)];
        acc.x = fmaf(mv, vv.x, acc.x);
        acc.y = fmaf(mv, vv.y, acc.y);
        acc.z = fmaf(mv, vv.z, acc.z);
        acc.w = fmaf(mv, vv.w, acc.w);
    }
    ((float4*)(g_x + (long)bm * DM))[tid] = acc;
}

// ============================================================
extern "C" void kernel_launch(void* const* d_in, const int* in_sizes, int n_in,
                              void* d_out, int out_size)
{
    const float* query = (const float*)d_in[0];
    const float* value = (const float*)d_in[1];
    const float* kedge = (const float*)d_in[2];
    const float* adjm  = (const float*)d_in[3];
    const int*   mask  = (const int*)  d_in[4];
    const float* Wq = (const float*)d_in[5];
    const float* bq = (const float*)d_in[6];
    const float* Wk = (const float*)d_in[7];
    const float* bk = (const float*)d_in[8];
    const float* Wv = (const float*)d_in[9];
    const float* bv = (const float*)d_in[10];
    const float* Wo = (const float*)d_in[11];
    const float* bo = (const float*)d_in[12];
    const float* We = (const float*)d_in[13];
    const float* be = (const float*)d_in[14];
    const float* lam = (const float*)d_in[15];

    float* x_out = (float*)d_out;
    float* e_out = (float*)d_out + (long)BATCH * NB * DM;

    float *p_k, *p_q, *p_v, *p_msg, *p_x;
    __nv_bfloat16 *p_wkh, *p_wkl;
    __half *p_weh16, *p_wel16;
    cudaGetSymbolAddress((void**)&p_k,   g_k);
    cudaGetSymbolAddress((void**)&p_q,   g_q);
    cudaGetSymbolAddress((void**)&p_v,   g_v);
    cudaGetSymbolAddress((void**)&p_msg, g_msg);
    cudaGetSymbolAddress((void**)&p_x,   g_x);
    cudaGetSymbolAddress((void**)&p_wkh, g_wkh);
    cudaGetSymbolAddress((void**)&p_wkl, g_wkl);
    cudaGetSymbolAddress((void**)&p_weh16, g_weh16);
    cudaGetSymbolAddress((void**)&p_wel16, g_wel16);

    cudaFuncSetAttribute(mma_gemm,     cudaFuncAttributeMaxDynamicSharedMemorySize, SMTOT);
    cudaFuncSetAttribute(mma_gemm_f16, cudaFuncAttributeMaxDynamicSharedMemorySize, SMTOT2);

    const int Erows = BATCH * NB * NB;       // 131072

    dim3 blk(256);
    dim3 gqv(DM / 64, BATCH * NB / 64, 2);   // (8, 16, 2): q and v batched
    dim3 gx (DM / 64, BATCH * NB / 64, 1);
    dim3 gbig(DM / 128, Erows / 128);        // (4, 1024)

    // weight splits (both in one launch)
    wsplit_kernel<<<dim3(DM * DM / 256, 2), 256>>>(Wk, We);

    // q and v projections in one batched launch
    sgemm64<<<gqv, blk>>>(query, value, Wq, Wv, bq, bv, p_q, p_v);

    // k = key_edge @ Wk + bk  (HMMA split-bf16, 3-term, 2 CTA/SM)
    mma_gemm<<<gbig, blk, SMTOT>>>(kedge, p_wkh, p_wkl, bk, p_k);

    // scores: n-split x4 for occupancy
    scores_kernel<<<dim3(BATCH * NB, 4), 128>>>();
    message_kernel<<<BATCH * HEADS * NB, 128>>>(adjm, mask, lam);
    nodeh_kernel<<<BATCH * NB, 128>>>();

    sgemm64<<<gx, blk>>>(p_x, p_x, Wo, Wo, bo, bo, x_out, x_out);

    // e_out = (msg ⊙ k) @ We + be  (2-term fp16, scaled by 1024)
    mma_gemm_f16<<<gbig, blk, SMTOT2>>>(p_k, p_weh16, p_wel16, be, e_out, p_msg);
}

// round 17
// speedup vs baseline: 1.3085x; 1.1147x over previous
#include <cuda_runtime.h>
#include <cuda_bf16.h>
#include <cuda_fp16.h>
#include <math.h>
#include <stdint.h>

#define NB     128
#define BATCH  8
#define HEADS  16
#define DM     512
#define DKH    32

// ---- scratch (device globals: no allocation allowed) ----
__device__ float g_k   [(long)BATCH*NB*NB*DM];   // 268 MB: k = key_edge@Wk+bk, layout (b,m,n,d)
__device__ float g_q   [BATCH*NB*DM];
__device__ float g_v   [BATCH*NB*DM];
__device__ float g_outS[BATCH*HEADS*NB*NB];      // out_scores (b,h,m,n)
__device__ float g_inS [BATCH*HEADS*NB*NB];      // in_scores stored transposed: (b,h,n,m)
__device__ float g_msg [BATCH*HEADS*NB*NB];      // message*adj (b,h,m,n)
__device__ float g_x   [BATCH*NB*DM];            // node_hidden (b,m,d)

// split+transposed weights (fp16 hi/lo): W*[n][k]
__device__ __half g_wkh16[DM*DM];
__device__ __half g_wkl16[DM*DM];
__device__ __half g_weh16[DM*DM];
__device__ __half g_wel16[DM*DM];

// ============================================================
// helpers
// ============================================================
__device__ __forceinline__ uint32_t smem_u32(const void* p) {
    uint32_t a;
    asm("{ .reg .u64 t; cvta.to.shared.u64 t, %1; cvt.u32.u64 %0, t; }" : "=r"(a) : "l"(p));
    return a;
}
__device__ __forceinline__ void cp16(uint32_t dst, const void* src) {
    asm volatile("cp.async.cg.shared.global [%0], [%1], 16;" :: "r"(dst), "l"(src) : "memory");
}
#define CP_COMMIT() asm volatile("cp.async.commit_group;" ::: "memory")
#define CP_WAIT0()  asm volatile("cp.async.wait_group 0;" ::: "memory")

#define LDMX4(r, a) \
    asm volatile("ldmatrix.sync.aligned.m8n8.x4.shared.b16 {%0,%1,%2,%3}, [%4];" \
        : "=r"((r)[0]), "=r"((r)[1]), "=r"((r)[2]), "=r"((r)[3]) : "r"(a))

__device__ __forceinline__ uint32_t pack_f16(float x, float y) {
    uint32_t r;
    asm("cvt.rn.f16x2.f32 %0, %1, %2;" : "=r"(r) : "f"(y), "f"(x));
    return r;
}

// m16n8k16 row.col fp16 -> f32 accumulate
__device__ __forceinline__ void mma_f16(float* d, const uint32_t* a, const uint32_t* b) {
    asm volatile(
        "mma.sync.aligned.m16n8k16.row.col.f32.f16.f16.f32 "
        "{%0,%1,%2,%3}, {%4,%5,%6,%7}, {%8,%9}, {%0,%1,%2,%3};"
        : "+f"(d[0]), "+f"(d[1]), "+f"(d[2]), "+f"(d[3])
        : "r"(a[0]), "r"(a[1]), "r"(a[2]), "r"(a[3]), "r"(b[0]), "r"(b[1]));
}

// ============================================================
// Weight prep: W -> transposed fp16 hi/lo.  blockIdx.y selects Wk/We.
// ============================================================
__global__ void wsplit_kernel(const float* __restrict__ Wk,
                              const float* __restrict__ We)
{
    int i = blockIdx.x * 256 + threadIdx.x;   // i = k*512 + n
    int k = i >> 9, n = i & 511;
    const float* W = blockIdx.y ? We : Wk;
    __half* Wh = blockIdx.y ? g_weh16 : g_wkh16;
    __half* Wl = blockIdx.y ? g_wel16 : g_wkl16;
    float x = W[i];
    __half h = __float2half(x);
    float r = x - __half2float(h);
    Wh[n * DM + k] = h;
    Wl[n * DM + k] = __float2half(r);
}

// ============================================================
// 2-term fp16 HMMA GEMM: C[M,512] = A[M,512] @ Wt^T + bias
//   A as single fp16 (optionally msg-scaled x1024); B split fp16 hi/lo.
//   CTA 128x128, warp 64x32, k-chunk 32, double-buffered, ldmatrix,
//   2 CTA/SM.  Per warp per k32: 64 MMA + 16 ldmatrix.
// ============================================================
#define APITCH 80
#define STAGE  (128 * APITCH)       // 10240 B per array
#define SMTOT2 (2 * 3 * STAGE)      // 61440 B

template<bool USE_MSG>
__global__ __launch_bounds__(256, 2)
void mma_gemm_f16(const float* __restrict__ A,
                  const __half* __restrict__ Bhp,
                  const __half* __restrict__ Blp,
                  const float* __restrict__ bias,
                  float* __restrict__ C,
                  const float* __restrict__ msg)
{
    extern __shared__ __align__(16) uint8_t dsm[];
    const uint32_t sb = smem_u32(dsm);

    const int tid = threadIdx.x;
    const int wid = tid >> 5, lid = tid & 31;
    const int wm = wid & 1, wn = wid >> 1;
    const int g  = lid >> 2, tg = lid & 3;
    const int n0 = blockIdx.x * 128;
    const long m0 = (long)blockIdx.y * 128;

    const int ar = tid >> 1, ahalf = tid & 1;
    const long agr = m0 + ar;
    const float* Abase = A + agr * DM + ahalf * 16;
    long msgb = 0;
    if (USE_MSG) msgb = (((agr >> 14) * (long)HEADS) << 14) + (agr & 16383);

    const uint32_t a_lane = (uint32_t)((lid & 15) * APITCH + (lid >> 4) * 16);
    const uint32_t b_lane = (uint32_t)((((lid & 7) + ((lid & 16) ? 8 : 0)) * APITCH) + ((lid & 8) ? 16 : 0));
    const uint32_t a_warp = (uint32_t)(wm * 64 * APITCH);
    const uint32_t b_warp = (uint32_t)(wn * 32 * APITCH);

    float acc[4][4][4];
#pragma unroll
    for (int mi = 0; mi < 4; mi++)
#pragma unroll
        for (int ni = 0; ni < 4; ni++)
#pragma unroll
            for (int r = 0; r < 4; r++) acc[mi][ni][r] = 0.f;

    float areg[16];

    auto LDA = [&](int c) {
        const float* p = Abase + c * 32;
#pragma unroll
        for (int q = 0; q < 4; q++) {
            float4 v = *(const float4*)(p + q * 4);
            areg[q * 4 + 0] = v.x; areg[q * 4 + 1] = v.y;
            areg[q * 4 + 2] = v.z; areg[q * 4 + 3] = v.w;
        }
        if (USE_MSG) {
            const float s = msg[msgb + ((long)c << 14)] * 1024.f;  // fp16-normal range
#pragma unroll
            for (int i = 0; i < 16; i++) areg[i] *= s;
        }
    };
    auto STA = [&](int s) {
        uint32_t ph[8];
#pragma unroll
        for (int i = 0; i < 8; i++) ph[i] = pack_f16(areg[2*i], areg[2*i+1]);
        const uint32_t dh = sb + (uint32_t)(s * 3 * STAGE) + (uint32_t)(ar * APITCH + ahalf * 32);
        asm volatile("st.shared.v4.b32 [%0], {%1,%2,%3,%4};" :: "r"(dh),      "r"(ph[0]), "r"(ph[1]), "r"(ph[2]), "r"(ph[3]) : "memory");
        asm volatile("st.shared.v4.b32 [%0], {%1,%2,%3,%4};" :: "r"(dh + 16), "r"(ph[4]), "r"(ph[5]), "r"(ph[6]), "r"(ph[7]) : "memory");
    };
    auto CPB = [&](int c, int s) {
        const uint32_t db = sb + (uint32_t)(s * 3 * STAGE) + (uint32_t)STAGE;
#pragma unroll
        for (int q = 0; q < 2; q++) {
            int u = q * 256 + tid;
            int row = u >> 2, seg = u & 3;
            uint32_t d = db + (uint32_t)(row * APITCH + seg * 16);
            long so = (long)(n0 + row) * DM + c * 32 + seg * 8;
            cp16(d, Bhp + so);
            cp16(d + STAGE, Blp + so);
        }
    };

    auto COMPUTE = [&](int s) {
        const uint32_t base = sb + (uint32_t)(s * 3 * STAGE);
        const uint32_t pA  = base + a_warp + a_lane;
        const uint32_t pBh = base + (uint32_t)STAGE + b_warp + b_lane;
        const uint32_t pBl = pBh + (uint32_t)STAGE;
#pragma unroll
        for (int ks = 0; ks < 2; ks++) {
            const uint32_t ko = (uint32_t)(ks * 32);
            uint32_t af[4][4], bh[4][2];
#pragma unroll
            for (int mi = 0; mi < 4; mi++)
                LDMX4(af[mi], pA + ko + (uint32_t)(mi * 16 * APITCH));
#pragma unroll
            for (int p = 0; p < 2; p++) {
                uint32_t r[4];
                LDMX4(r, pBh + ko + (uint32_t)(p * 16 * APITCH));
                bh[2*p][0] = r[0]; bh[2*p][1] = r[1];
                bh[2*p+1][0] = r[2]; bh[2*p+1][1] = r[3];
            }
#pragma unroll
            for (int mi = 0; mi < 4; mi++)
#pragma unroll
                for (int ni = 0; ni < 4; ni++) mma_f16(acc[mi][ni], af[mi], bh[ni]);
#pragma unroll
            for (int p = 0; p < 2; p++) {
                uint32_t r[4];
                LDMX4(r, pBl + ko + (uint32_t)(p * 16 * APITCH));
                bh[2*p][0] = r[0]; bh[2*p][1] = r[1];
                bh[2*p+1][0] = r[2]; bh[2*p+1][1] = r[3];
            }
#pragma unroll
            for (int mi = 0; mi < 4; mi++)
#pragma unroll
                for (int ni = 0; ni < 4; ni++) mma_f16(acc[mi][ni], af[mi], bh[ni]);
        }
    };

    LDA(0);
    CPB(0, 0); CP_COMMIT();
    STA(0);
    CP_WAIT0(); __syncthreads();
#pragma unroll 1
    for (int c = 0; c < 16; c++) {
        const int s = c & 1;
        const bool more = (c < 15);
        if (more) { CPB(c + 1, s ^ 1); CP_COMMIT(); LDA(c + 1); }
        COMPUTE(s);
        if (more) { STA(s ^ 1); CP_WAIT0(); }
        __syncthreads();
    }

    const float inv = USE_MSG ? (1.f / 1024.f) : 1.f;
#pragma unroll
    for (int ni = 0; ni < 4; ni++) {
        const int col = n0 + wn * 32 + ni * 8 + tg * 2;
        const float b0 = bias[col], b1 = bias[col + 1];
#pragma unroll
        for (int mi = 0; mi < 4; mi++) {
            const long row = m0 + wm * 64 + mi * 16 + g;
            float2 o0 = make_float2(acc[mi][ni][0] * inv + b0, acc[mi][ni][1] * inv + b1);
            float2 o1 = make_float2(acc[mi][ni][2] * inv + b0, acc[mi][ni][3] * inv + b1);
            *(float2*)(C + row * DM + col)       = o0;
            *(float2*)(C + (row + 8) * DM + col) = o1;
        }
    }
}

// ============================================================
// fp32 SGEMM 64x64 tiles for the small projections (M=1024)
// ============================================================
__global__ __launch_bounds__(256)
void sgemm64(const float* __restrict__ A0, const float* __restrict__ A1,
             const float* __restrict__ W0, const float* __restrict__ W1,
             const float* __restrict__ b0p, const float* __restrict__ b1p,
             float* __restrict__ C0, float* __restrict__ C1)
{
    const float* A    = blockIdx.z ? A1 : A0;
    const float* B    = blockIdx.z ? W1 : W0;
    const float* bias = blockIdx.z ? b1p : b0p;
    float*       C    = blockIdx.z ? C1 : C0;

    __shared__ float As[16][64];
    __shared__ float Bs[16][64];

    const int tid = threadIdx.x;
    const int m0 = blockIdx.y * 64, n0 = blockIdx.x * 64;
    const int tx = tid & 15, ty = tid >> 4;

    const int aRow = tid >> 2, aCol = (tid & 3) * 4;
    const int bRow = tid >> 4, bCol = (tid & 15) * 4;

    float acc[4][4];
#pragma unroll
    for (int i = 0; i < 4; i++)
#pragma unroll
        for (int j = 0; j < 4; j++) acc[i][j] = 0.f;

    const float* Ap = A + (long)(m0 + aRow) * DM + aCol;
    const float* Bp = B + (long)bRow * DM + n0 + bCol;

    for (int k0 = 0; k0 < DM; k0 += 16) {
        float4 av = *(const float4*)(Ap + k0);
        As[aCol + 0][aRow] = av.x;
        As[aCol + 1][aRow] = av.y;
        As[aCol + 2][aRow] = av.z;
        As[aCol + 3][aRow] = av.w;
        *(float4*)&Bs[bRow][bCol] = *(const float4*)(Bp + (long)k0 * DM);
        __syncthreads();
#pragma unroll
        for (int kk = 0; kk < 16; kk++) {
            float4 a4 = *(float4*)&As[kk][ty * 4];
            float4 b4 = *(float4*)&Bs[kk][tx * 4];
            float ar[4] = {a4.x, a4.y, a4.z, a4.w};
            float br[4] = {b4.x, b4.y, b4.z, b4.w};
#pragma unroll
            for (int i = 0; i < 4; i++)
#pragma unroll
                for (int j = 0; j < 4; j++) acc[i][j] = fmaf(ar[i], br[j], acc[i][j]);
        }
        __syncthreads();
    }

    const int c = n0 + tx * 4;
    const float4 bz = *(const float4*)&bias[c];
#pragma unroll
    for (int i = 0; i < 4; i++) {
        const long r = m0 + ty * 4 + i;
        float4 o;
        o.x = acc[i][0] + bz.x; o.y = acc[i][1] + bz.y;
        o.z = acc[i][2] + bz.z; o.w = acc[i][3] + bz.w;
        *(float4*)&C[r * DM + c] = o;
    }
}

// ============================================================
// Scores (n-split x4 for occupancy)
// ============================================================
__global__ void scores_kernel()
{
    const int bm = blockIdx.x;
    const int b  = bm >> 7, m = bm & 127;
    const int n_lo = blockIdx.y * 32;
    const int tid = threadIdx.x;
    __shared__ float qm[DM];

    ((float4*)qm)[tid] = ((const float4*)(g_q + (long)bm * DM))[tid];
    __syncthreads();
    const float4 q4 = ((float4*)qm)[tid];
    const int h = tid >> 3;
    const float scale = 0.17677669529663687f;

    const float4* krow0 = (const float4*)(g_k + (long)bm * NB * DM) + tid;
    const float4* qb    = (const float4*)(g_q + (long)b * NB * DM) + tid;

    for (int n = n_lo; n < n_lo + 32; n++) {
        const float4 k4  = krow0[(long)n * (DM / 4)];
        const float4 qn4 = qb[(long)n * (DM / 4)];
        float po = k4.x*q4.x  + k4.y*q4.y  + k4.z*q4.z  + k4.w*q4.w;
        float pi = k4.x*qn4.x + k4.y*qn4.y + k4.z*qn4.z + k4.w*qn4.w;
#pragma unroll
        for (int o = 4; o; o >>= 1) {
            po += __shfl_xor_sync(0xffffffffu, po, o);
            pi += __shfl_xor_sync(0xffffffffu, pi, o);
        }
        if ((tid & 7) == 0) {
            g_outS[(((long)b*HEADS + h)*NB + m)*NB + n] = po * scale;
            g_inS [(((long)b*HEADS + h)*NB + n)*NB + m] = pi * scale;
        }
    }
}

// ============================================================
// Softmax + message + adj weighting.
// ============================================================
__device__ __forceinline__ float bredmax(float v, float* sm)
{
#pragma unroll
    for (int o = 16; o; o >>= 1) v = fmaxf(v, __shfl_xor_sync(0xffffffffu, v, o));
    if ((threadIdx.x & 31) == 0) sm[threadIdx.x >> 5] = v;
    __syncthreads();
    float r = fmaxf(fmaxf(sm[0], sm[1]), fmaxf(sm[2], sm[3]));
    __syncthreads();
    return r;
}
__device__ __forceinline__ float bredsum(float v, float* sm)
{
#pragma unroll
    for (int o = 16; o; o >>= 1) v += __shfl_xor_sync(0xffffffffu, v, o);
    if ((threadIdx.x & 31) == 0) sm[threadIdx.x >> 5] = v;
    __syncthreads();
    float r = sm[0] + sm[1] + sm[2] + sm[3];
    __syncthreads();
    return r;
}

__global__ void message_kernel(const float* __restrict__ adjm,
                               const int* __restrict__ mask,
                               const float* __restrict__ lam_p)
{
    const long row = blockIdx.x;
    const int i  = row & 127;
    const int b  = (int)(row >> 11);
    const int j  = threadIdx.x;
    const float lam = *lam_p;
    __shared__ float red[4];

    const int mk = mask[b * NB + j];
    const long base = row * NB;
    float so = g_outS[base + j];
    float si = g_inS [base + j];
    float aj = -lam * adjm[((long)b * NB + i) * NB + j];
    const float NEG = -3.0e38f;
    if (mk == 0) { so = NEG; si = NEG; aj = NEG; }

    const float mo = bredmax(so, red);
    const float mi = bredmax(si, red);
    const float ma = bredmax(aj, red);
    const float eo = (mk == 0) ? 0.f : expf(so - mo);
    const float ei = (mk == 0) ? 0.f : expf(si - mi);
    const float ea = (mk == 0) ? 0.f : expf(aj - ma);
    const float sumo = bredsum(eo, red);
    const float sumi = bredsum(ei, red);
    const float suma = bredsum(ea, red);

    const float oa = eo / sumo;
    const float ia = ei / sumi;
    const float aw = ea / suma;
    const float msgv = (j == i) ? ia : (oa + ia);
    g_msg[base + j] = msgv * aw;
}

// ============================================================
// node_hidden
// ============================================================
__global__ void nodeh_kernel()
{
    const int bm = blockIdx.x;
    const int b = bm >> 7, m = bm & 127;
    const int tid = threadIdx.x;
    const int h = tid >> 3;
    const long mbase = (((long)b * HEADS + h) * NB + m) * NB;
    const float4* vp = (const float4*)(g_v + (long)b * NB * DM) + tid;

    float4 acc = make_float4(0.f, 0.f, 0.f, 0.f);
    for (int n = 0; n < NB; n++) {
        const float mv = g_msg[mbase + n];
        const float4 vv = vp[(long)n * (DM / 4)];
        acc.x = fmaf(mv, vv.x, acc.x);
        acc.y = fmaf(mv, vv.y, acc.y);
        acc.z = fmaf(mv, vv.z, acc.z);
        acc.w = fmaf(mv, vv.w, acc.w);
    }
    ((float4*)(g_x + (long)bm * DM))[tid] = acc;
}

// ============================================================
extern "C" void kernel_launch(void* const* d_in, const int* in_sizes, int n_in,
                              void* d_out, int out_size)
{
    const float* query = (const float*)d_in[0];
    const float* value = (const float*)d_in[1];
    const float* kedge = (const float*)d_in[2];
    const float* adjm  = (const float*)d_in[3];
    const int*   mask  = (const int*)  d_in[4];
    const float* Wq = (const float*)d_in[5];
    const float* bq = (const float*)d_in[6];
    const float* Wk = (const float*)d_in[7];
    const float* bk = (const float*)d_in[8];
    const float* Wv = (const float*)d_in[9];
    const float* bv = (const float*)d_in[10];
    const float* Wo = (const float*)d_in[11];
    const float* bo = (const float*)d_in[12];
    const float* We = (const float*)d_in[13];
    const float* be = (const float*)d_in[14];
    const float* lam = (const float*)d_in[15];

    float* x_out = (float*)d_out;
    float* e_out = (float*)d_out + (long)BATCH * NB * DM;

    float *p_k, *p_q, *p_v, *p_msg, *p_x;
    __half *p_wkh16, *p_wkl16, *p_weh16, *p_wel16;
    cudaGetSymbolAddress((void**)&p_k,   g_k);
    cudaGetSymbolAddress((void**)&p_q,   g_q);
    cudaGetSymbolAddress((void**)&p_v,   g_v);
    cudaGetSymbolAddress((void**)&p_msg, g_msg);
    cudaGetSymbolAddress((void**)&p_x,   g_x);
    cudaGetSymbolAddress((void**)&p_wkh16, g_wkh16);
    cudaGetSymbolAddress((void**)&p_wkl16, g_wkl16);
    cudaGetSymbolAddress((void**)&p_weh16, g_weh16);
    cudaGetSymbolAddress((void**)&p_wel16, g_wel16);

    cudaFuncSetAttribute(mma_gemm_f16<false>, cudaFuncAttributeMaxDynamicSharedMemorySize, SMTOT2);
    cudaFuncSetAttribute(mma_gemm_f16<true>,  cudaFuncAttributeMaxDynamicSharedMemorySize, SMTOT2);

    const int Erows = BATCH * NB * NB;       // 131072

    dim3 blk(256);
    dim3 gqv(DM / 64, BATCH * NB / 64, 2);   // (8, 16, 2): q and v batched
    dim3 gx (DM / 64, BATCH * NB / 64, 1);
    dim3 gbig(DM / 128, Erows / 128);        // (4, 1024)

    // weight splits (both in one launch, fp16 hi/lo)
    wsplit_kernel<<<dim3(DM * DM / 256, 2), 256>>>(Wk, We);

    // q and v projections in one batched launch
    sgemm64<<<gqv, blk>>>(query, value, Wq, Wv, bq, bv, p_q, p_v);

    // k = key_edge @ Wk + bk  (2-term fp16)
    mma_gemm_f16<false><<<gbig, blk, SMTOT2>>>(kedge, p_wkh16, p_wkl16, bk, p_k, nullptr);

    // scores: n-split x4 for occupancy
    scores_kernel<<<dim3(BATCH * NB, 4), 128>>>();
    message_kernel<<<BATCH * HEADS * NB, 128>>>(adjm, mask, lam);
    nodeh_kernel<<<BATCH * NB, 128>>>();

    sgemm64<<<gx, blk>>>(p_x, p_x, Wo, Wo, bo, bo, x_out, x_out);

    // e_out = (msg ⊙ k) @ We + be  (2-term fp16, msg scaled by 1024)
    mma_gemm_f16<true><<<gbig, blk, SMTOT2>>>(p_k, p_weh16, p_wel16, be, e_out, p_msg);
}